// round 10
// baseline (speedup 1.0000x reference)
#include <cuda_runtime.h>
#include <cuda_bf16.h>
#include <cstdint>

// Problem constants
constexpr int B   = 4;
constexpr int S   = 2048;
constexpr int HID = 512;
constexpr int NH  = 8;
constexpr int DH  = 64;
constexpr int M   = B * S;       // 8192

// Scratch (device globals — no runtime allocation allowed)
__device__ __nv_bfloat16 g_wh[4][HID * HID];
__device__ uint8_t g_w8[4][HID * HID], g_wl8[4][HID * HID];
__device__ __nv_bfloat16 g_qh[M * HID], g_ql[M * HID];
__device__ __nv_bfloat16 g_kh[M * HID], g_kl[M * HID];
__device__ __nv_bfloat16 g_vh[M * HID], g_vl[M * HID];
__device__ __nv_bfloat16 g_oh[M * HID];
__device__ uint8_t g_o8[M * HID], g_ol8[M * HID];

// ---------------------------------------------------------------------------
// mma.sync / ldmatrix / cp.async / fp8-cvt helpers (plain sm_80/89 PTX)
// ---------------------------------------------------------------------------
__device__ __forceinline__ uint32_t smem_u32(const void* p) {
  uint32_t a;
  asm("{ .reg .u64 t; cvta.to.shared.u64 t, %1; cvt.u32.u64 %0, t; }"
      : "=r"(a) : "l"(p));
  return a;
}

#define LDMX4(r0, r1, r2, r3, addr)                                       \
  asm volatile(                                                           \
      "ldmatrix.sync.aligned.m8n8.x4.shared.b16 {%0,%1,%2,%3}, [%4];"     \
      : "=r"(r0), "=r"(r1), "=r"(r2), "=r"(r3) : "r"(addr))

#define LDMX4T(r0, r1, r2, r3, addr)                                      \
  asm volatile(                                                           \
      "ldmatrix.sync.aligned.m8n8.x4.trans.shared.b16 {%0,%1,%2,%3}, [%4];" \
      : "=r"(r0), "=r"(r1), "=r"(r2), "=r"(r3) : "r"(addr))

#define CP_ASYNC16(dst, src)                                              \
  asm volatile("cp.async.cg.shared.global [%0], [%1], 16;" ::             \
                   "r"(dst), "l"(src))
#define CP_COMMIT() asm volatile("cp.async.commit_group;" ::: "memory")
#define CP_WAIT0() asm volatile("cp.async.wait_group 0;" ::: "memory")

__device__ __forceinline__ void mma_bf16(float& c0, float& c1, float& c2,
                                         float& c3, uint32_t a0, uint32_t a1,
                                         uint32_t a2, uint32_t a3,
                                         uint32_t b0, uint32_t b1) {
  asm volatile(
      "mma.sync.aligned.m16n8k16.row.col.f32.bf16.bf16.f32 "
      "{%0,%1,%2,%3}, {%4,%5,%6,%7}, {%8,%9}, {%0,%1,%2,%3};"
      : "+f"(c0), "+f"(c1), "+f"(c2), "+f"(c3)
      : "r"(a0), "r"(a1), "r"(a2), "r"(a3), "r"(b0), "r"(b1));
}

// fp8 k32 MMAs, fp32 accumulate. A e4m3 x B e5m2 and A e5m2 x B e4m3.
__device__ __forceinline__ void mma_45(float& c0, float& c1, float& c2,
                                       float& c3, uint32_t a0, uint32_t a1,
                                       uint32_t a2, uint32_t a3, uint32_t b0,
                                       uint32_t b1) {
  asm volatile(
      "mma.sync.aligned.m16n8k32.row.col.f32.e4m3.e5m2.f32 "
      "{%0,%1,%2,%3}, {%4,%5,%6,%7}, {%8,%9}, {%0,%1,%2,%3};"
      : "+f"(c0), "+f"(c1), "+f"(c2), "+f"(c3)
      : "r"(a0), "r"(a1), "r"(a2), "r"(a3), "r"(b0), "r"(b1));
}
__device__ __forceinline__ void mma_54(float& c0, float& c1, float& c2,
                                       float& c3, uint32_t a0, uint32_t a1,
                                       uint32_t a2, uint32_t a3, uint32_t b0,
                                       uint32_t b1) {
  asm volatile(
      "mma.sync.aligned.m16n8k32.row.col.f32.e5m2.e4m3.f32 "
      "{%0,%1,%2,%3}, {%4,%5,%6,%7}, {%8,%9}, {%0,%1,%2,%3};"
      : "+f"(c0), "+f"(c1), "+f"(c2), "+f"(c3)
      : "r"(a0), "r"(a1), "r"(a2), "r"(a3), "r"(b0), "r"(b1));
}

__device__ __forceinline__ uint32_t pack_bf16(float a, float b) {
  __nv_bfloat162 t = __floats2bfloat162_rn(a, b);
  return *(uint32_t*)&t;
}
__device__ __forceinline__ uint16_t pack2_e4m3(float f0, float f1) {
  uint16_t r;
  asm("cvt.rn.satfinite.e4m3x2.f32 %0, %1, %2;" : "=h"(r) : "f"(f1), "f"(f0));
  return r;
}
__device__ __forceinline__ uint16_t pack2_e5m2(float f0, float f1) {
  uint16_t r;
  asm("cvt.rn.satfinite.e5m2x2.f32 %0, %1, %2;" : "=h"(r) : "f"(f1), "f"(f0));
  return r;
}
__device__ __forceinline__ uint32_t pack4_e4m3(float f0, float f1, float f2,
                                               float f3) {
  return (uint32_t)pack2_e4m3(f0, f1) | ((uint32_t)pack2_e4m3(f2, f3) << 16);
}
__device__ __forceinline__ uint32_t pack4_e5m2(float f0, float f1, float f2,
                                               float f3) {
  return (uint32_t)pack2_e5m2(f0, f1) | ((uint32_t)pack2_e5m2(f2, f3) << 16);
}

// ---------------------------------------------------------------------------
// Weight split: fp32 -> bf16 hi + e4m3(full) + e5m2(lo). Batched (grid.y).
// ---------------------------------------------------------------------------
struct SplitBatch {
  const float* src[4];
  __nv_bfloat16* hi[4];
  uint8_t* f8[4];
  uint8_t* l8[4];
};

__global__ __launch_bounds__(256) void split_batch_kernel(SplitBatch sb,
                                                          int n4) {
  int i = blockIdx.x * blockDim.x + threadIdx.x;
  if (i >= n4) return;
  int z = blockIdx.y;
  float4 v = ((const float4*)sb.src[z])[i];
  float hx = __bfloat162float(__float2bfloat16(v.x));
  float hy = __bfloat162float(__float2bfloat16(v.y));
  float hz = __bfloat162float(__float2bfloat16(v.z));
  float hw = __bfloat162float(__float2bfloat16(v.w));
  uint2 ho;
  ho.x = pack_bf16(v.x, v.y);
  ho.y = pack_bf16(v.z, v.w);
  ((uint2*)sb.hi[z])[i] = ho;
  ((uint32_t*)sb.f8[z])[i] = pack4_e4m3(v.x, v.y, v.z, v.w);
  ((uint32_t*)sb.l8[z])[i] =
      pack4_e5m2(v.x - hx, v.y - hy, v.z - hz, v.w - hw);
}

// ---------------------------------------------------------------------------
// GEMM-NT with fp32-equivalent accuracy via bf16 main + fp8 corrections:
//   C = Ah*Wh (bf16 k16) + A8*Wl8 (e4m3 x e5m2, k32) + Al8*W8 (e5m2 x e4m3)
// e5m2's 5-bit exponent holds the lo terms unscaled, so all three accumulate
// into ONE fp32 accumulator. 4 tensor-pipe slots per k32 vs 6 for bf16x3.
// CTA 128x128, 8 warps, warp 64x32. grid.z batches GEMMs.
// ---------------------------------------------------------------------------
constexpr int RS = 72;                     // bf16 tile row stride (144 B)
constexpr int RB8 = 80;                    // fp8 tile row stride (bytes)
constexpr int BT16 = 128 * RS * 2;         // 18432
constexpr int BT8 = 128 * RB8;             // 10240
constexpr int SA_H = 0;
constexpr int SA8 = SA_H + BT16;           // 18432
constexpr int SAL8 = SA8 + BT8;            // 28672
constexpr int SW_H = SAL8 + BT8;           // 38912
constexpr int SW8 = SW_H + BT16;           // 57344
constexpr int SWL8 = SW8 + BT8;            // 67584
constexpr int GEMM_SMEM = SWL8 + BT8;      // 77824 (x2 CTAs fits)

struct GemmBatch {
  const float* af[3];                 // AFP32 inputs
  const __nv_bfloat16* ah;            // !AFP32 (out-proj) A operands
  const uint8_t* a8;
  const uint8_t* al8;
  const __nv_bfloat16* wh[3];
  const uint8_t* w8[3];
  const uint8_t* wl8[3];
  __nv_bfloat16* ch[3];               // SPLIT outputs (bf16 hi/lo)
  __nv_bfloat16* cl[3];
  float* c;                           // !SPLIT output
};

template <bool AFP32, bool SPLIT>
__global__ __launch_bounds__(256, 2) void gemm_tc_hmma(GemmBatch p) {
  extern __shared__ __align__(128) char smem[];
  const uint32_t sb = smem_u32(smem);
  const int t = threadIdx.x;
  const int wid = t >> 5, l = t & 31;
  const int wm = wid >> 2;
  const int wn = wid & 3;
  const int m0 = blockIdx.y * 128;
  const int n0 = blockIdx.x * 128;
  const int z = blockIdx.z;

  const __nv_bfloat16* Wh = p.wh[z];
  const uint8_t* W8g = p.w8[z];
  const uint8_t* Wl8g = p.wl8[z];

  float acc[4][4][4] = {};

  const int a_row = (l & 15);
  const int a_koff = ((l >> 4) & 1) * 16;
  const int b_row = (l & 7) + ((l >> 4) & 1) * 8;
  const int b_koff = ((l >> 3) & 1) * 16;

  for (int kc = 0; kc < 8; kc++) {
    const int koff = kc * 64;
    __syncthreads();
    // --- A tiles (bf16 hi + e4m3 full + e5m2 lo) ---
    if constexpr (AFP32) {
      const float* Af = p.af[z];
#pragma unroll
      for (int i = 0; i < 8; i++) {     // 2048 float4
        int v = t + i * 256;
        int row = v >> 4, c = v & 15;
        float4 fv = *(const float4*)(Af + (size_t)(m0 + row) * HID + koff +
                                     c * 4);
        float hx = __bfloat162float(__float2bfloat16(fv.x));
        float hy = __bfloat162float(__float2bfloat16(fv.y));
        float hz = __bfloat162float(__float2bfloat16(fv.z));
        float hw = __bfloat162float(__float2bfloat16(fv.w));
        uint2 ho;
        ho.x = pack_bf16(fv.x, fv.y);
        ho.y = pack_bf16(fv.z, fv.w);
        *(uint2*)(smem + SA_H + row * (RS * 2) + c * 8) = ho;
        *(uint32_t*)(smem + SA8 + row * RB8 + c * 4) =
            pack4_e4m3(fv.x, fv.y, fv.z, fv.w);
        *(uint32_t*)(smem + SAL8 + row * RB8 + c * 4) =
            pack4_e5m2(fv.x - hx, fv.y - hy, fv.z - hz, fv.w - hw);
      }
    } else {
#pragma unroll
      for (int i = 0; i < 4; i++) {     // bf16 hi: 1024 uint4
        int v = t + i * 256;
        int row = v >> 3, c = v & 7;
        *(uint4*)(smem + SA_H + row * (RS * 2) + c * 16) =
            *(const uint4*)(p.ah + (size_t)(m0 + row) * HID + koff + c * 8);
      }
#pragma unroll
      for (int i = 0; i < 2; i++) {     // fp8: 512 uint4 each
        int v = t + i * 256;
        int row = v >> 2, c = v & 3;
        size_t g = (size_t)(m0 + row) * HID + koff + c * 16;
        *(uint4*)(smem + SA8 + row * RB8 + c * 16) =
            *(const uint4*)(p.a8 + g);
        *(uint4*)(smem + SAL8 + row * RB8 + c * 16) =
            *(const uint4*)(p.al8 + g);
      }
    }
    // --- W tiles ---
#pragma unroll
    for (int i = 0; i < 4; i++) {
      int v = t + i * 256;
      int row = v >> 3, c = v & 7;
      *(uint4*)(smem + SW_H + row * (RS * 2) + c * 16) =
          *(const uint4*)(Wh + (size_t)(n0 + row) * HID + koff + c * 8);
    }
#pragma unroll
    for (int i = 0; i < 2; i++) {
      int v = t + i * 256;
      int row = v >> 2, c = v & 3;
      size_t g = (size_t)(n0 + row) * HID + koff + c * 16;
      *(uint4*)(smem + SW8 + row * RB8 + c * 16) = *(const uint4*)(W8g + g);
      *(uint4*)(smem + SWL8 + row * RB8 + c * 16) = *(const uint4*)(Wl8g + g);
    }
    __syncthreads();

#pragma unroll
    for (int ks32 = 0; ks32 < 2; ks32++) {
      const int kb8 = ks32 * 32;
      // --- main bf16: two k16 halves ---
#pragma unroll
      for (int h16 = 0; h16 < 2; h16++) {
        const int kb = (ks32 * 2 + h16) * 32;
        uint32_t ah[4][4], bh[8];
#pragma unroll
        for (int mt = 0; mt < 4; mt++) {
          uint32_t ra = (wm * 64 + mt * 16 + a_row) * (RS * 2) + kb + a_koff;
          LDMX4(ah[mt][0], ah[mt][1], ah[mt][2], ah[mt][3], sb + SA_H + ra);
        }
#pragma unroll
        for (int np = 0; np < 2; np++) {
          uint32_t rb = (wn * 32 + np * 16 + b_row) * (RS * 2) + kb + b_koff;
          LDMX4(bh[np * 4 + 0], bh[np * 4 + 1], bh[np * 4 + 2],
                bh[np * 4 + 3], sb + SW_H + rb);
        }
#pragma unroll
        for (int mt = 0; mt < 4; mt++)
#pragma unroll
          for (int nt = 0; nt < 4; nt++) {
            float* c = acc[mt][nt];
            mma_bf16(c[0], c[1], c[2], c[3], ah[mt][0], ah[mt][1], ah[mt][2],
                     ah[mt][3], bh[nt * 2], bh[nt * 2 + 1]);
          }
      }
      // --- correction 1: A8 (e4m3) x Wl8 (e5m2), k32 ---
      {
        uint32_t a8f[4][4], b8[8];
#pragma unroll
        for (int mt = 0; mt < 4; mt++) {
          uint32_t ra = (wm * 64 + mt * 16 + a_row) * RB8 + kb8 + a_koff;
          LDMX4(a8f[mt][0], a8f[mt][1], a8f[mt][2], a8f[mt][3], sb + SA8 + ra);
        }
#pragma unroll
        for (int np = 0; np < 2; np++) {
          uint32_t rb = (wn * 32 + np * 16 + b_row) * RB8 + kb8 + b_koff;
          LDMX4(b8[np * 4 + 0], b8[np * 4 + 1], b8[np * 4 + 2],
                b8[np * 4 + 3], sb + SWL8 + rb);
        }
#pragma unroll
        for (int mt = 0; mt < 4; mt++)
#pragma unroll
          for (int nt = 0; nt < 4; nt++) {
            float* c = acc[mt][nt];
            mma_45(c[0], c[1], c[2], c[3], a8f[mt][0], a8f[mt][1],
                   a8f[mt][2], a8f[mt][3], b8[nt * 2], b8[nt * 2 + 1]);
          }
      }
      // --- correction 2: Al8 (e5m2) x W8 (e4m3), k32 ---
      {
        uint32_t alf[4][4], b8[8];
#pragma unroll
        for (int mt = 0; mt < 4; mt++) {
          uint32_t ra = (wm * 64 + mt * 16 + a_row) * RB8 + kb8 + a_koff;
          LDMX4(alf[mt][0], alf[mt][1], alf[mt][2], alf[mt][3],
                sb + SAL8 + ra);
        }
#pragma unroll
        for (int np = 0; np < 2; np++) {
          uint32_t rb = (wn * 32 + np * 16 + b_row) * RB8 + kb8 + b_koff;
          LDMX4(b8[np * 4 + 0], b8[np * 4 + 1], b8[np * 4 + 2],
                b8[np * 4 + 3], sb + SW8 + rb);
        }
#pragma unroll
        for (int mt = 0; mt < 4; mt++)
#pragma unroll
          for (int nt = 0; nt < 4; nt++) {
            float* c = acc[mt][nt];
            mma_54(c[0], c[1], c[2], c[3], alf[mt][0], alf[mt][1],
                   alf[mt][2], alf[mt][3], b8[nt * 2], b8[nt * 2 + 1]);
          }
      }
    }
  }

  const int er = l >> 2, ec = (l & 3) * 2;
#pragma unroll
  for (int mt = 0; mt < 4; mt++) {
    int row = m0 + wm * 64 + mt * 16 + er;
#pragma unroll
    for (int nt = 0; nt < 4; nt++) {
      int col = n0 + wn * 32 + nt * 8 + ec;
      float* a = acc[mt][nt];
      if constexpr (SPLIT) {
        float h0 = __bfloat162float(__float2bfloat16(a[0]));
        float h1 = __bfloat162float(__float2bfloat16(a[1]));
        float h2 = __bfloat162float(__float2bfloat16(a[2]));
        float h3 = __bfloat162float(__float2bfloat16(a[3]));
        size_t i0 = (size_t)row * HID + col;
        size_t i1 = (size_t)(row + 8) * HID + col;
        *(uint32_t*)&p.ch[z][i0] = pack_bf16(a[0], a[1]);
        *(uint32_t*)&p.cl[z][i0] = pack_bf16(a[0] - h0, a[1] - h1);
        *(uint32_t*)&p.ch[z][i1] = pack_bf16(a[2], a[3]);
        *(uint32_t*)&p.cl[z][i1] = pack_bf16(a[2] - h2, a[3] - h3);
      } else {
        *(float2*)&p.c[(size_t)row * HID + col] = make_float2(a[0], a[1]);
        *(float2*)&p.c[(size_t)(row + 8) * HID + col] =
            make_float2(a[2], a[3]);
      }
    }
  }
}

// ---------------------------------------------------------------------------
// HMMA flash attention (bf16x3, exp2-domain softmax) — internals unchanged
// from round 9; epilogue now also emits e4m3(O) + e5m2(O-Oh) for the fp8
// out-projection.
// ---------------------------------------------------------------------------
constexpr float SC2 = 0.125f * 1.4426950408889634f;  // (1/8)*log2(e)

constexpr int AQ_H = 0;
constexpr int AQ_L = 128 * RS * 2;
constexpr int STG0 = 2 * 128 * RS * 2;         // 36864
constexpr int KV_COMP = 64 * RS * 2;           // 9216
constexpr int STG_SZ = 4 * KV_COMP;            // 36864
constexpr int ATTN_SMEM = STG0 + 2 * STG_SZ;   // 110592

__global__ __launch_bounds__(256, 2) void attn_hmma(
    const __nv_bfloat16* __restrict__ Qh, const __nv_bfloat16* __restrict__ Ql,
    const __nv_bfloat16* __restrict__ Kh, const __nv_bfloat16* __restrict__ Kl,
    const __nv_bfloat16* __restrict__ Vh, const __nv_bfloat16* __restrict__ Vl,
    const int* __restrict__ valid_lens, __nv_bfloat16* __restrict__ Oh,
    uint8_t* __restrict__ O8, uint8_t* __restrict__ Ol8) {
  extern __shared__ __align__(128) char smem[];
  const uint32_t sb = smem_u32(smem);
  const int qt = blockIdx.x, h = blockIdx.y, b = blockIdx.z;
  const int t = threadIdx.x;
  const int wid = t >> 5, l = t & 31;
  const int q0 = qt * 128;
  const int vlen = valid_lens[b];
  const int ntiles = (vlen + 63) >> 6;

  const __nv_bfloat16* kv_src[4] = {Kh, Kl, Vh, Vl};

  auto issue_tile = [&](int stage, int kbase) {
#pragma unroll
    for (int i = 0; i < 8; i++) {
      int idx = t + i * 256;
      int comp = idx >> 9;
      int r = (idx >> 3) & 63;
      int c = idx & 7;
      const __nv_bfloat16* src =
          kv_src[comp] + (size_t)(b * S + kbase + r) * HID + h * DH + c * 8;
      uint32_t dst =
          sb + STG0 + stage * STG_SZ + comp * KV_COMP + r * (RS * 2) + c * 16;
      CP_ASYNC16(dst, src);
    }
  };

  issue_tile(0, 0);
  CP_COMMIT();
#pragma unroll
  for (int i = 0; i < 4; i++) {
    int v = t + i * 256;
    int row = v >> 3, c = v & 7;
    size_t g = (size_t)(b * S + q0 + row) * HID + h * DH + c * 8;
    uint32_t so = row * (RS * 2) + c * 16;
    *(uint4*)(smem + AQ_H + so) = *(const uint4*)(Qh + g);
    *(uint4*)(smem + AQ_L + so) = *(const uint4*)(Ql + g);
  }
  __syncthreads();

  const int a_row = (l & 15);
  const int a_koff = ((l >> 4) & 1) * 16;
  const int b_row = (l & 7) + ((l >> 4) & 1) * 8;
  const int b_koff = ((l >> 3) & 1) * 16;
  const int v_row = (l & 7) + ((l >> 3) & 1) * 8;
  const int v_col = ((l >> 4) & 1) * 16;
  const int cb = (l & 3) * 2;

  uint32_t qh[4][4], ql[4][4];
#pragma unroll
  for (int ks = 0; ks < 4; ks++) {
    uint32_t ra = (wid * 16 + a_row) * (RS * 2) + ks * 32 + a_koff;
    LDMX4(qh[ks][0], qh[ks][1], qh[ks][2], qh[ks][3], sb + AQ_H + ra);
    LDMX4(ql[ks][0], ql[ks][1], ql[ks][2], ql[ks][3], sb + AQ_L + ra);
  }

  float oacc[8][4] = {};
  float m0r = -1e30f, m1r = -1e30f, l0r = 0.f, l1r = 0.f;

  for (int kt = 0; kt < ntiles; kt++) {
    const int kbase = kt * 64;
    const uint32_t kb_h = sb + STG0 + (kt & 1) * STG_SZ;
    const uint32_t kb_l = kb_h + KV_COMP;
    const uint32_t vb_h = kb_h + 2 * KV_COMP;
    const uint32_t vb_l = kb_h + 3 * KV_COMP;

    CP_WAIT0();
    __syncthreads();
    if (kt + 1 < ntiles) {
      issue_tile((kt + 1) & 1, kbase + 64);
      CP_COMMIT();
    }

    float sc[8][4];
#pragma unroll
    for (int nt = 0; nt < 8; nt++)
#pragma unroll
      for (int c = 0; c < 4; c++) sc[nt][c] = 0.f;
#pragma unroll
    for (int ks = 0; ks < 4; ks++) {
      uint32_t khf[16], klf[16];
#pragma unroll
      for (int np = 0; np < 4; np++) {
        uint32_t rb = (np * 16 + b_row) * (RS * 2) + ks * 32 + b_koff;
        LDMX4(khf[np * 4 + 0], khf[np * 4 + 1], khf[np * 4 + 2],
              khf[np * 4 + 3], kb_h + rb);
        LDMX4(klf[np * 4 + 0], klf[np * 4 + 1], klf[np * 4 + 2],
              klf[np * 4 + 3], kb_l + rb);
      }
#pragma unroll
      for (int nt = 0; nt < 8; nt++) {
        float* c = sc[nt];
        mma_bf16(c[0], c[1], c[2], c[3], qh[ks][0], qh[ks][1], qh[ks][2],
                 qh[ks][3], khf[nt * 2], khf[nt * 2 + 1]);
        mma_bf16(c[0], c[1], c[2], c[3], qh[ks][0], qh[ks][1], qh[ks][2],
                 qh[ks][3], klf[nt * 2], klf[nt * 2 + 1]);
        mma_bf16(c[0], c[1], c[2], c[3], ql[ks][0], ql[ks][1], ql[ks][2],
                 ql[ks][3], khf[nt * 2], khf[nt * 2 + 1]);
      }
    }

#pragma unroll
    for (int nt = 0; nt < 8; nt++)
#pragma unroll
      for (int c = 0; c < 4; c++) sc[nt][c] *= SC2;
    if (kbase + 64 > vlen) {
#pragma unroll
      for (int nt = 0; nt < 8; nt++) {
        int k0 = kbase + nt * 8 + cb;
        if (k0 >= vlen) { sc[nt][0] = -1e30f; sc[nt][2] = -1e30f; }
        if (k0 + 1 >= vlen) { sc[nt][1] = -1e30f; sc[nt][3] = -1e30f; }
      }
    }

    float rm0 = -1e30f, rm1 = -1e30f;
#pragma unroll
    for (int nt = 0; nt < 8; nt++) {
      rm0 = fmaxf(rm0, fmaxf(sc[nt][0], sc[nt][1]));
      rm1 = fmaxf(rm1, fmaxf(sc[nt][2], sc[nt][3]));
    }
    rm0 = fmaxf(rm0, __shfl_xor_sync(0xffffffffu, rm0, 1));
    rm0 = fmaxf(rm0, __shfl_xor_sync(0xffffffffu, rm0, 2));
    rm1 = fmaxf(rm1, __shfl_xor_sync(0xffffffffu, rm1, 1));
    rm1 = fmaxf(rm1, __shfl_xor_sync(0xffffffffu, rm1, 2));
    float mn0 = fmaxf(m0r, rm0), mn1 = fmaxf(m1r, rm1);
    float corr0 = exp2f(m0r - mn0), corr1 = exp2f(m1r - mn1);

    uint32_t ph[8][2], pl[8][2];
    float rs0 = 0.f, rs1 = 0.f;
#pragma unroll
    for (int nt = 0; nt < 8; nt++) {
      float p0 = exp2f(sc[nt][0] - mn0);
      float p1 = exp2f(sc[nt][1] - mn0);
      float p2 = exp2f(sc[nt][2] - mn1);
      float p3 = exp2f(sc[nt][3] - mn1);
      rs0 += p0 + p1;
      rs1 += p2 + p3;
      float h0 = __bfloat162float(__float2bfloat16(p0));
      float h1 = __bfloat162float(__float2bfloat16(p1));
      float h2 = __bfloat162float(__float2bfloat16(p2));
      float h3 = __bfloat162float(__float2bfloat16(p3));
      ph[nt][0] = pack_bf16(p0, p1);
      ph[nt][1] = pack_bf16(p2, p3);
      pl[nt][0] = pack_bf16(p0 - h0, p1 - h1);
      pl[nt][1] = pack_bf16(p2 - h2, p3 - h3);
    }
    rs0 += __shfl_xor_sync(0xffffffffu, rs0, 1);
    rs0 += __shfl_xor_sync(0xffffffffu, rs0, 2);
    rs1 += __shfl_xor_sync(0xffffffffu, rs1, 1);
    rs1 += __shfl_xor_sync(0xffffffffu, rs1, 2);
    l0r = l0r * corr0 + rs0;
    l1r = l1r * corr1 + rs1;
    m0r = mn0;
    m1r = mn1;
#pragma unroll
    for (int nt = 0; nt < 8; nt++) {
      oacc[nt][0] *= corr0;
      oacc[nt][1] *= corr0;
      oacc[nt][2] *= corr1;
      oacc[nt][3] *= corr1;
    }

#pragma unroll
    for (int ks = 0; ks < 4; ks++) {
      uint32_t vhf[16], vlf[16];
#pragma unroll
      for (int np = 0; np < 4; np++) {
        uint32_t rv = (ks * 16 + v_row) * (RS * 2) + np * 32 + v_col;
        LDMX4T(vhf[np * 4 + 0], vhf[np * 4 + 1], vhf[np * 4 + 2],
               vhf[np * 4 + 3], vb_h + rv);
        LDMX4T(vlf[np * 4 + 0], vlf[np * 4 + 1], vlf[np * 4 + 2],
               vlf[np * 4 + 3], vb_l + rv);
      }
      uint32_t a0 = ph[2 * ks][0], a1 = ph[2 * ks][1];
      uint32_t a2 = ph[2 * ks + 1][0], a3 = ph[2 * ks + 1][1];
      uint32_t e0 = pl[2 * ks][0], e1 = pl[2 * ks][1];
      uint32_t e2 = pl[2 * ks + 1][0], e3 = pl[2 * ks + 1][1];
#pragma unroll
      for (int nt = 0; nt < 8; nt++) {
        float* c = oacc[nt];
        mma_bf16(c[0], c[1], c[2], c[3], a0, a1, a2, a3, vhf[nt * 2],
                 vhf[nt * 2 + 1]);
        mma_bf16(c[0], c[1], c[2], c[3], a0, a1, a2, a3, vlf[nt * 2],
                 vlf[nt * 2 + 1]);
        mma_bf16(c[0], c[1], c[2], c[3], e0, e1, e2, e3, vhf[nt * 2],
                 vhf[nt * 2 + 1]);
      }
    }
  }

  float inv0 = 1.f / l0r, inv1 = 1.f / l1r;
  int r0 = q0 + wid * 16 + (l >> 2);
#pragma unroll
  for (int nt = 0; nt < 8; nt++) {
    int col = h * DH + nt * 8 + cb;
    float o0 = oacc[nt][0] * inv0, o1 = oacc[nt][1] * inv0;
    float o2 = oacc[nt][2] * inv1, o3 = oacc[nt][3] * inv1;
    float h0 = __bfloat162float(__float2bfloat16(o0));
    float h1 = __bfloat162float(__float2bfloat16(o1));
    float h2 = __bfloat162float(__float2bfloat16(o2));
    float h3 = __bfloat162float(__float2bfloat16(o3));
    size_t i0 = (size_t)(b * S + r0) * HID + col;
    size_t i1 = (size_t)(b * S + r0 + 8) * HID + col;
    *(uint32_t*)&Oh[i0] = pack_bf16(o0, o1);
    *(uint32_t*)&Oh[i1] = pack_bf16(o2, o3);
    *(uint16_t*)&O8[i0] = pack2_e4m3(o0, o1);
    *(uint16_t*)&O8[i1] = pack2_e4m3(o2, o3);
    *(uint16_t*)&Ol8[i0] = pack2_e5m2(o0 - h0, o1 - h1);
    *(uint16_t*)&Ol8[i1] = pack2_e5m2(o2 - h2, o3 - h3);
  }
}

// ---------------------------------------------------------------------------
extern "C" void kernel_launch(void* const* d_in, const int* in_sizes, int n_in,
                              void* d_out, int out_size) {
  const float* queries = (const float*)d_in[0];
  const float* keys    = (const float*)d_in[1];
  const float* values  = (const float*)d_in[2];
  const int*   vlens   = (const int*)d_in[3];
  const float* W[4]    = {(const float*)d_in[4], (const float*)d_in[5],
                          (const float*)d_in[6], (const float*)d_in[7]};
  float* out = (float*)d_out;

  __nv_bfloat16 *whb, *qh, *ql, *kh, *kl, *vh, *vl, *oh;
  uint8_t *w8b, *wl8b, *o8, *ol8;
  cudaGetSymbolAddress((void**)&whb, g_wh);
  cudaGetSymbolAddress((void**)&w8b, g_w8);
  cudaGetSymbolAddress((void**)&wl8b, g_wl8);
  cudaGetSymbolAddress((void**)&qh, g_qh);
  cudaGetSymbolAddress((void**)&ql, g_ql);
  cudaGetSymbolAddress((void**)&kh, g_kh);
  cudaGetSymbolAddress((void**)&kl, g_kl);
  cudaGetSymbolAddress((void**)&vh, g_vh);
  cudaGetSymbolAddress((void**)&vl, g_vl);
  cudaGetSymbolAddress((void**)&oh, g_oh);
  cudaGetSymbolAddress((void**)&o8, g_o8);
  cudaGetSymbolAddress((void**)&ol8, g_ol8);
  const int WSZ = HID * HID;

  cudaFuncSetAttribute(gemm_tc_hmma<true, true>,
                       cudaFuncAttributeMaxDynamicSharedMemorySize, GEMM_SMEM);
  cudaFuncSetAttribute(gemm_tc_hmma<false, false>,
                       cudaFuncAttributeMaxDynamicSharedMemorySize, GEMM_SMEM);
  cudaFuncSetAttribute(attn_hmma,
                       cudaFuncAttributeMaxDynamicSharedMemorySize, ATTN_SMEM);

  // --- one batched weight split (Wq, Wk, Wv, Wo) ---
  SplitBatch wsb = {};
  for (int i = 0; i < 4; i++) {
    wsb.src[i] = W[i];
    wsb.hi[i] = whb + i * WSZ;
    wsb.f8[i] = w8b + i * WSZ;
    wsb.l8[i] = wl8b + i * WSZ;
  }
  split_batch_kernel<<<dim3(WSZ / 4 / 256, 4), 256>>>(wsb, WSZ / 4);

  // --- Q/K/V projections in ONE launch (grid.z = 3) ---
  GemmBatch gp = {};
  gp.af[0] = queries; gp.af[1] = keys; gp.af[2] = values;
  for (int i = 0; i < 3; i++) {
    gp.wh[i] = whb + i * WSZ;
    gp.w8[i] = w8b + i * WSZ;
    gp.wl8[i] = wl8b + i * WSZ;
  }
  gp.ch[0] = qh; gp.cl[0] = ql;
  gp.ch[1] = kh; gp.cl[1] = kl;
  gp.ch[2] = vh; gp.cl[2] = vl;
  gemm_tc_hmma<true, true>
      <<<dim3(HID / 128, M / 128, 3), 256, GEMM_SMEM>>>(gp);

  // --- attention ---
  attn_hmma<<<dim3(S / 128, NH, B), 256, ATTN_SMEM>>>(qh, ql, kh, kl, vh, vl,
                                                      vlens, oh, o8, ol8);

  // --- output projection (fp32 out) ---
  GemmBatch go = {};
  go.ah = oh; go.a8 = o8; go.al8 = ol8;
  go.wh[0] = whb + 3 * WSZ;
  go.w8[0] = w8b + 3 * WSZ;
  go.wl8[0] = wl8b + 3 * WSZ;
  go.c = out;
  gemm_tc_hmma<false, false>
      <<<dim3(HID / 128, M / 128, 1), 256, GEMM_SMEM>>>(go);
}

// round 11
// speedup vs baseline: 1.1295x; 1.1295x over previous
#include <cuda_runtime.h>
#include <cuda_bf16.h>
#include <cstdint>

// Problem constants
constexpr int B   = 4;
constexpr int S   = 2048;
constexpr int HID = 512;
constexpr int NH  = 8;
constexpr int DH  = 64;
constexpr int M   = B * S;       // 8192

// Scratch (device globals — no runtime allocation allowed)
__device__ __nv_bfloat16 g_wh[4][HID * HID], g_wl[4][HID * HID];
__device__ __nv_bfloat16 g_qh[M * HID], g_ql[M * HID];
__device__ __nv_bfloat16 g_kh[M * HID], g_kl[M * HID];
__device__ __nv_bfloat16 g_vh[M * HID], g_vl[M * HID];
__device__ __nv_bfloat16 g_oh[M * HID], g_ol[M * HID];

// ---------------------------------------------------------------------------
// mma.sync / ldmatrix / cp.async helpers (plain sm_80+ PTX)
// ---------------------------------------------------------------------------
__device__ __forceinline__ uint32_t smem_u32(const void* p) {
  uint32_t a;
  asm("{ .reg .u64 t; cvta.to.shared.u64 t, %1; cvt.u32.u64 %0, t; }"
      : "=r"(a) : "l"(p));
  return a;
}

#define LDMX4(r0, r1, r2, r3, addr)                                       \
  asm volatile(                                                           \
      "ldmatrix.sync.aligned.m8n8.x4.shared.b16 {%0,%1,%2,%3}, [%4];"     \
      : "=r"(r0), "=r"(r1), "=r"(r2), "=r"(r3) : "r"(addr))

#define LDMX4T(r0, r1, r2, r3, addr)                                      \
  asm volatile(                                                           \
      "ldmatrix.sync.aligned.m8n8.x4.trans.shared.b16 {%0,%1,%2,%3}, [%4];" \
      : "=r"(r0), "=r"(r1), "=r"(r2), "=r"(r3) : "r"(addr))

#define CP_ASYNC16(dst, src)                                              \
  asm volatile("cp.async.cg.shared.global [%0], [%1], 16;" ::             \
                   "r"(dst), "l"(src))
#define CP_COMMIT() asm volatile("cp.async.commit_group;" ::: "memory")
#define CP_WAIT0() asm volatile("cp.async.wait_group 0;" ::: "memory")
#define CP_WAIT1() asm volatile("cp.async.wait_group 1;" ::: "memory")

__device__ __forceinline__ void mma_bf16(float& c0, float& c1, float& c2,
                                         float& c3, uint32_t a0, uint32_t a1,
                                         uint32_t a2, uint32_t a3,
                                         uint32_t b0, uint32_t b1) {
  asm volatile(
      "mma.sync.aligned.m16n8k16.row.col.f32.bf16.bf16.f32 "
      "{%0,%1,%2,%3}, {%4,%5,%6,%7}, {%8,%9}, {%0,%1,%2,%3};"
      : "+f"(c0), "+f"(c1), "+f"(c2), "+f"(c3)
      : "r"(a0), "r"(a1), "r"(a2), "r"(a3), "r"(b0), "r"(b1));
}

__device__ __forceinline__ uint32_t pack_bf16(float a, float b) {
  __nv_bfloat162 t = __floats2bfloat162_rn(a, b);
  return *(uint32_t*)&t;
}

// ---------------------------------------------------------------------------
// fp32 -> (bf16 hi, bf16 lo) split, batched over blockIdx.y (weights).
// ---------------------------------------------------------------------------
struct SplitBatch {
  const float* src[4];
  __nv_bfloat16* hi[4];
  __nv_bfloat16* lo[4];
};

__global__ __launch_bounds__(256) void split_batch_kernel(SplitBatch sb,
                                                          int n4) {
  int i = blockIdx.x * blockDim.x + threadIdx.x;
  if (i >= n4) return;
  int z = blockIdx.y;
  float4 v = ((const float4*)sb.src[z])[i];
  float hx = __bfloat162float(__float2bfloat16(v.x));
  float hy = __bfloat162float(__float2bfloat16(v.y));
  float hz = __bfloat162float(__float2bfloat16(v.z));
  float hw = __bfloat162float(__float2bfloat16(v.w));
  uint2 ho, lw;
  ho.x = pack_bf16(v.x, v.y);
  ho.y = pack_bf16(v.z, v.w);
  lw.x = pack_bf16(v.x - hx, v.y - hy);
  lw.y = pack_bf16(v.z - hz, v.w - hw);
  ((uint2*)sb.hi[z])[i] = ho;
  ((uint2*)sb.lo[z])[i] = lw;
}

// ---------------------------------------------------------------------------
// HMMA bf16x3 GEMM-NT: C = A @ W^T with fp32-equivalent accuracy.
// (round-9 structure — at the measured mma.sync rate ceiling)
// ---------------------------------------------------------------------------
constexpr int RS = 72;                    // smem row stride in bf16 (144 B)
constexpr int TILE_BYTES = 128 * RS * 2;  // 18432 per tile
constexpr int SA_H = 0;
constexpr int SA_L = TILE_BYTES;
constexpr int SW_BASE = 2 * TILE_BYTES;   // 36864
constexpr int W_STG = 2 * TILE_BYTES;     // Wh+Wl per stage
constexpr int GEMM_SMEM = SW_BASE + 2 * W_STG;  // 110592

struct GemmBatch {
  const float* af[3];                 // AFP32 inputs
  const __nv_bfloat16* ah;            // !AFP32 input (out-proj)
  const __nv_bfloat16* al;
  const __nv_bfloat16* wh[3];
  const __nv_bfloat16* wl[3];
  __nv_bfloat16* ch[3];               // SPLIT outputs
  __nv_bfloat16* cl[3];
  float* c;                           // !SPLIT output
};

template <bool AFP32, bool SPLIT>
__global__ __launch_bounds__(256, 2) void gemm_tc_hmma(GemmBatch p) {
  extern __shared__ __align__(128) char smem[];
  const uint32_t sb = smem_u32(smem);
  const int t = threadIdx.x;
  const int wid = t >> 5, l = t & 31;
  const int wm = wid >> 2;
  const int wn = wid & 3;
  const int m0 = blockIdx.y * 128;
  const int n0 = blockIdx.x * 128;
  const int z = blockIdx.z;

  const __nv_bfloat16* Wh = p.wh[z];
  const __nv_bfloat16* Wl = p.wl[z];

  auto issue_w = [&](int stage, int kc) {
    const int koff = kc * 64;
#pragma unroll
    for (int i = 0; i < 8; i++) {
      int idx = t + i * 256;
      int comp = idx >> 10;             // 0: Wh, 1: Wl
      int r = (idx >> 3) & 127;
      int c = idx & 7;
      const __nv_bfloat16* src =
          (comp ? Wl : Wh) + (size_t)(n0 + r) * HID + koff + c * 8;
      uint32_t dst = sb + SW_BASE + stage * W_STG + comp * TILE_BYTES +
                     r * (RS * 2) + c * 16;
      CP_ASYNC16(dst, src);
    }
  };

  issue_w(0, 0);
  CP_COMMIT();

  float acc[4][4][4] = {};

  const int a_row = (l & 15);
  const int a_koff = ((l >> 4) & 1) * 16;
  const int b_row = (l & 7) + ((l >> 4) & 1) * 8;
  const int b_koff = ((l >> 3) & 1) * 16;

  for (int kc = 0; kc < 8; kc++) {
    const int koff = kc * 64;
    if constexpr (AFP32) {
      const float* Af = p.af[z];
#pragma unroll
      for (int i = 0; i < 8; i++) {     // 2048 float4
        int v = t + i * 256;
        int row = v >> 4, c = v & 15;
        float4 fv = *(const float4*)(Af + (size_t)(m0 + row) * HID + koff +
                                     c * 4);
        float hx = __bfloat162float(__float2bfloat16(fv.x));
        float hy = __bfloat162float(__float2bfloat16(fv.y));
        float hz = __bfloat162float(__float2bfloat16(fv.z));
        float hw = __bfloat162float(__float2bfloat16(fv.w));
        uint2 ho, lw;
        ho.x = pack_bf16(fv.x, fv.y);
        ho.y = pack_bf16(fv.z, fv.w);
        lw.x = pack_bf16(fv.x - hx, fv.y - hy);
        lw.y = pack_bf16(fv.z - hz, fv.w - hw);
        uint32_t so = row * (RS * 2) + c * 8;
        *(uint2*)(smem + SA_H + so) = ho;
        *(uint2*)(smem + SA_L + so) = lw;
      }
    } else {
#pragma unroll
      for (int i = 0; i < 8; i++) {     // 2048 x 16B cp.async
        int idx = t + i * 256;
        int comp = idx >> 10;           // 0: Ah, 1: Al
        int r = (idx >> 3) & 127;
        int c = idx & 7;
        const __nv_bfloat16* src =
            (comp ? p.al : p.ah) + (size_t)(m0 + r) * HID + koff + c * 8;
        uint32_t dst = sb + comp * TILE_BYTES + r * (RS * 2) + c * 16;
        CP_ASYNC16(dst, src);
      }
      CP_COMMIT();
    }
    if (kc + 1 < 8) {
      issue_w((kc + 1) & 1, kc + 1);
      CP_COMMIT();
      CP_WAIT1();
    } else {
      CP_WAIT0();
    }
    __syncthreads();
    const uint32_t st_w = sb + SW_BASE + (kc & 1) * W_STG;

#pragma unroll
    for (int ks = 0; ks < 4; ks++) {
      const int kb = ks * 32;
      uint32_t ah[4][4], al[4][4], bh[8], bl[8];
#pragma unroll
      for (int mt = 0; mt < 4; mt++) {
        uint32_t ra = (wm * 64 + mt * 16 + a_row) * (RS * 2) + kb + a_koff;
        LDMX4(ah[mt][0], ah[mt][1], ah[mt][2], ah[mt][3], sb + SA_H + ra);
        LDMX4(al[mt][0], al[mt][1], al[mt][2], al[mt][3], sb + SA_L + ra);
      }
#pragma unroll
      for (int np = 0; np < 2; np++) {
        uint32_t rb = (wn * 32 + np * 16 + b_row) * (RS * 2) + kb + b_koff;
        LDMX4(bh[np * 4 + 0], bh[np * 4 + 1], bh[np * 4 + 2], bh[np * 4 + 3],
              st_w + rb);
        LDMX4(bl[np * 4 + 0], bl[np * 4 + 1], bl[np * 4 + 2], bl[np * 4 + 3],
              st_w + TILE_BYTES + rb);
      }
#pragma unroll
      for (int mt = 0; mt < 4; mt++)
#pragma unroll
        for (int nt = 0; nt < 4; nt++) {
          float* c = acc[mt][nt];
          mma_bf16(c[0], c[1], c[2], c[3], ah[mt][0], ah[mt][1], ah[mt][2],
                   ah[mt][3], bh[nt * 2], bh[nt * 2 + 1]);
          mma_bf16(c[0], c[1], c[2], c[3], ah[mt][0], ah[mt][1], ah[mt][2],
                   ah[mt][3], bl[nt * 2], bl[nt * 2 + 1]);
          mma_bf16(c[0], c[1], c[2], c[3], al[mt][0], al[mt][1], al[mt][2],
                   al[mt][3], bh[nt * 2], bh[nt * 2 + 1]);
        }
    }
    __syncthreads();
  }

  const int er = l >> 2, ec = (l & 3) * 2;
#pragma unroll
  for (int mt = 0; mt < 4; mt++) {
    int row = m0 + wm * 64 + mt * 16 + er;
#pragma unroll
    for (int nt = 0; nt < 4; nt++) {
      int col = n0 + wn * 32 + nt * 8 + ec;
      float* a = acc[mt][nt];
      if constexpr (SPLIT) {
        float h0 = __bfloat162float(__float2bfloat16(a[0]));
        float h1 = __bfloat162float(__float2bfloat16(a[1]));
        float h2 = __bfloat162float(__float2bfloat16(a[2]));
        float h3 = __bfloat162float(__float2bfloat16(a[3]));
        size_t i0 = (size_t)row * HID + col;
        size_t i1 = (size_t)(row + 8) * HID + col;
        *(uint32_t*)&p.ch[z][i0] = pack_bf16(a[0], a[1]);
        *(uint32_t*)&p.cl[z][i0] = pack_bf16(a[0] - h0, a[1] - h1);
        *(uint32_t*)&p.ch[z][i1] = pack_bf16(a[2], a[3]);
        *(uint32_t*)&p.cl[z][i1] = pack_bf16(a[2] - h2, a[3] - h3);
      } else {
        *(float2*)&p.c[(size_t)row * HID + col] = make_float2(a[0], a[1]);
        *(float2*)&p.c[(size_t)(row + 8) * HID + col] =
            make_float2(a[2], a[3]);
      }
    }
  }
}

// ---------------------------------------------------------------------------
// HMMA flash attention (bf16x3, exp2-domain softmax).
// Grid: (B*NH, S/128) with b = blockIdx.x & 3 (b FASTEST) — every scheduling
// wave carries a uniform batch mix, so the random per-batch valid_len no
// longer creates a single-batch tail wave (old layout: b slowest, wave 2 was
// all of batches 2-3).
// ---------------------------------------------------------------------------
constexpr float SC2 = 0.125f * 1.4426950408889634f;  // (1/8)*log2(e)

constexpr int AQ_H = 0;
constexpr int AQ_L = 128 * RS * 2;
constexpr int STG0 = 2 * 128 * RS * 2;         // 36864
constexpr int KV_COMP = 64 * RS * 2;           // 9216
constexpr int STG_SZ = 4 * KV_COMP;            // 36864
constexpr int ATTN_SMEM = STG0 + 2 * STG_SZ;   // 110592

__global__ __launch_bounds__(256, 2) void attn_hmma(
    const __nv_bfloat16* __restrict__ Qh, const __nv_bfloat16* __restrict__ Ql,
    const __nv_bfloat16* __restrict__ Kh, const __nv_bfloat16* __restrict__ Kl,
    const __nv_bfloat16* __restrict__ Vh, const __nv_bfloat16* __restrict__ Vl,
    const int* __restrict__ valid_lens, __nv_bfloat16* __restrict__ Oh,
    __nv_bfloat16* __restrict__ Ol) {
  extern __shared__ __align__(128) char smem[];
  const uint32_t sb = smem_u32(smem);
  const int b = blockIdx.x & (B - 1);       // batch fastest
  const int h = blockIdx.x >> 2;            // head
  const int qt = blockIdx.y;
  const int t = threadIdx.x;
  const int wid = t >> 5, l = t & 31;
  const int q0 = qt * 128;
  const int vlen = valid_lens[b];
  const int ntiles = (vlen + 63) >> 6;

  const __nv_bfloat16* kv_src[4] = {Kh, Kl, Vh, Vl};

  auto issue_tile = [&](int stage, int kbase) {
#pragma unroll
    for (int i = 0; i < 8; i++) {
      int idx = t + i * 256;
      int comp = idx >> 9;
      int r = (idx >> 3) & 63;
      int c = idx & 7;
      const __nv_bfloat16* src =
          kv_src[comp] + (size_t)(b * S + kbase + r) * HID + h * DH + c * 8;
      uint32_t dst =
          sb + STG0 + stage * STG_SZ + comp * KV_COMP + r * (RS * 2) + c * 16;
      CP_ASYNC16(dst, src);
    }
  };

  issue_tile(0, 0);
  CP_COMMIT();
#pragma unroll
  for (int i = 0; i < 4; i++) {
    int v = t + i * 256;
    int row = v >> 3, c = v & 7;
    size_t g = (size_t)(b * S + q0 + row) * HID + h * DH + c * 8;
    uint32_t so = row * (RS * 2) + c * 16;
    *(uint4*)(smem + AQ_H + so) = *(const uint4*)(Qh + g);
    *(uint4*)(smem + AQ_L + so) = *(const uint4*)(Ql + g);
  }
  __syncthreads();

  const int a_row = (l & 15);
  const int a_koff = ((l >> 4) & 1) * 16;
  const int b_row = (l & 7) + ((l >> 4) & 1) * 8;
  const int b_koff = ((l >> 3) & 1) * 16;
  const int v_row = (l & 7) + ((l >> 3) & 1) * 8;
  const int v_col = ((l >> 4) & 1) * 16;
  const int cb = (l & 3) * 2;

  uint32_t qh[4][4], ql[4][4];
#pragma unroll
  for (int ks = 0; ks < 4; ks++) {
    uint32_t ra = (wid * 16 + a_row) * (RS * 2) + ks * 32 + a_koff;
    LDMX4(qh[ks][0], qh[ks][1], qh[ks][2], qh[ks][3], sb + AQ_H + ra);
    LDMX4(ql[ks][0], ql[ks][1], ql[ks][2], ql[ks][3], sb + AQ_L + ra);
  }

  float oacc[8][4] = {};
  float m0r = -1e30f, m1r = -1e30f, l0r = 0.f, l1r = 0.f;

  for (int kt = 0; kt < ntiles; kt++) {
    const int kbase = kt * 64;
    const uint32_t kb_h = sb + STG0 + (kt & 1) * STG_SZ;
    const uint32_t kb_l = kb_h + KV_COMP;
    const uint32_t vb_h = kb_h + 2 * KV_COMP;
    const uint32_t vb_l = kb_h + 3 * KV_COMP;

    CP_WAIT0();
    __syncthreads();
    if (kt + 1 < ntiles) {
      issue_tile((kt + 1) & 1, kbase + 64);
      CP_COMMIT();
    }

    float sc[8][4];
#pragma unroll
    for (int nt = 0; nt < 8; nt++)
#pragma unroll
      for (int c = 0; c < 4; c++) sc[nt][c] = 0.f;
#pragma unroll
    for (int ks = 0; ks < 4; ks++) {
      uint32_t khf[16], klf[16];
#pragma unroll
      for (int np = 0; np < 4; np++) {
        uint32_t rb = (np * 16 + b_row) * (RS * 2) + ks * 32 + b_koff;
        LDMX4(khf[np * 4 + 0], khf[np * 4 + 1], khf[np * 4 + 2],
              khf[np * 4 + 3], kb_h + rb);
        LDMX4(klf[np * 4 + 0], klf[np * 4 + 1], klf[np * 4 + 2],
              klf[np * 4 + 3], kb_l + rb);
      }
#pragma unroll
      for (int nt = 0; nt < 8; nt++) {
        float* c = sc[nt];
        mma_bf16(c[0], c[1], c[2], c[3], qh[ks][0], qh[ks][1], qh[ks][2],
                 qh[ks][3], khf[nt * 2], khf[nt * 2 + 1]);
        mma_bf16(c[0], c[1], c[2], c[3], qh[ks][0], qh[ks][1], qh[ks][2],
                 qh[ks][3], klf[nt * 2], klf[nt * 2 + 1]);
        mma_bf16(c[0], c[1], c[2], c[3], ql[ks][0], ql[ks][1], ql[ks][2],
                 ql[ks][3], khf[nt * 2], khf[nt * 2 + 1]);
      }
    }

#pragma unroll
    for (int nt = 0; nt < 8; nt++)
#pragma unroll
      for (int c = 0; c < 4; c++) sc[nt][c] *= SC2;
    if (kbase + 64 > vlen) {
#pragma unroll
      for (int nt = 0; nt < 8; nt++) {
        int k0 = kbase + nt * 8 + cb;
        if (k0 >= vlen) { sc[nt][0] = -1e30f; sc[nt][2] = -1e30f; }
        if (k0 + 1 >= vlen) { sc[nt][1] = -1e30f; sc[nt][3] = -1e30f; }
      }
    }

    float rm0 = -1e30f, rm1 = -1e30f;
#pragma unroll
    for (int nt = 0; nt < 8; nt++) {
      rm0 = fmaxf(rm0, fmaxf(sc[nt][0], sc[nt][1]));
      rm1 = fmaxf(rm1, fmaxf(sc[nt][2], sc[nt][3]));
    }
    rm0 = fmaxf(rm0, __shfl_xor_sync(0xffffffffu, rm0, 1));
    rm0 = fmaxf(rm0, __shfl_xor_sync(0xffffffffu, rm0, 2));
    rm1 = fmaxf(rm1, __shfl_xor_sync(0xffffffffu, rm1, 1));
    rm1 = fmaxf(rm1, __shfl_xor_sync(0xffffffffu, rm1, 2));
    float mn0 = fmaxf(m0r, rm0), mn1 = fmaxf(m1r, rm1);
    float corr0 = exp2f(m0r - mn0), corr1 = exp2f(m1r - mn1);

    uint32_t ph[8][2], pl[8][2];
    float rs0 = 0.f, rs1 = 0.f;
#pragma unroll
    for (int nt = 0; nt < 8; nt++) {
      float p0 = exp2f(sc[nt][0] - mn0);
      float p1 = exp2f(sc[nt][1] - mn0);
      float p2 = exp2f(sc[nt][2] - mn1);
      float p3 = exp2f(sc[nt][3] - mn1);
      rs0 += p0 + p1;
      rs1 += p2 + p3;
      float h0 = __bfloat162float(__float2bfloat16(p0));
      float h1 = __bfloat162float(__float2bfloat16(p1));
      float h2 = __bfloat162float(__float2bfloat16(p2));
      float h3 = __bfloat162float(__float2bfloat16(p3));
      ph[nt][0] = pack_bf16(p0, p1);
      ph[nt][1] = pack_bf16(p2, p3);
      pl[nt][0] = pack_bf16(p0 - h0, p1 - h1);
      pl[nt][1] = pack_bf16(p2 - h2, p3 - h3);
    }
    rs0 += __shfl_xor_sync(0xffffffffu, rs0, 1);
    rs0 += __shfl_xor_sync(0xffffffffu, rs0, 2);
    rs1 += __shfl_xor_sync(0xffffffffu, rs1, 1);
    rs1 += __shfl_xor_sync(0xffffffffu, rs1, 2);
    l0r = l0r * corr0 + rs0;
    l1r = l1r * corr1 + rs1;
    m0r = mn0;
    m1r = mn1;
#pragma unroll
    for (int nt = 0; nt < 8; nt++) {
      oacc[nt][0] *= corr0;
      oacc[nt][1] *= corr0;
      oacc[nt][2] *= corr1;
      oacc[nt][3] *= corr1;
    }

#pragma unroll
    for (int ks = 0; ks < 4; ks++) {
      uint32_t vhf[16], vlf[16];
#pragma unroll
      for (int np = 0; np < 4; np++) {
        uint32_t rv = (ks * 16 + v_row) * (RS * 2) + np * 32 + v_col;
        LDMX4T(vhf[np * 4 + 0], vhf[np * 4 + 1], vhf[np * 4 + 2],
               vhf[np * 4 + 3], vb_h + rv);
        LDMX4T(vlf[np * 4 + 0], vlf[np * 4 + 1], vlf[np * 4 + 2],
               vlf[np * 4 + 3], vb_l + rv);
      }
      uint32_t a0 = ph[2 * ks][0], a1 = ph[2 * ks][1];
      uint32_t a2 = ph[2 * ks + 1][0], a3 = ph[2 * ks + 1][1];
      uint32_t e0 = pl[2 * ks][0], e1 = pl[2 * ks][1];
      uint32_t e2 = pl[2 * ks + 1][0], e3 = pl[2 * ks + 1][1];
#pragma unroll
      for (int nt = 0; nt < 8; nt++) {
        float* c = oacc[nt];
        mma_bf16(c[0], c[1], c[2], c[3], a0, a1, a2, a3, vhf[nt * 2],
                 vhf[nt * 2 + 1]);
        mma_bf16(c[0], c[1], c[2], c[3], a0, a1, a2, a3, vlf[nt * 2],
                 vlf[nt * 2 + 1]);
        mma_bf16(c[0], c[1], c[2], c[3], e0, e1, e2, e3, vhf[nt * 2],
                 vhf[nt * 2 + 1]);
      }
    }
  }

  float inv0 = 1.f / l0r, inv1 = 1.f / l1r;
  int r0 = q0 + wid * 16 + (l >> 2);
#pragma unroll
  for (int nt = 0; nt < 8; nt++) {
    int col = h * DH + nt * 8 + cb;
    float o0 = oacc[nt][0] * inv0, o1 = oacc[nt][1] * inv0;
    float o2 = oacc[nt][2] * inv1, o3 = oacc[nt][3] * inv1;
    float h0 = __bfloat162float(__float2bfloat16(o0));
    float h1 = __bfloat162float(__float2bfloat16(o1));
    float h2 = __bfloat162float(__float2bfloat16(o2));
    float h3 = __bfloat162float(__float2bfloat16(o3));
    size_t i0 = (size_t)(b * S + r0) * HID + col;
    size_t i1 = (size_t)(b * S + r0 + 8) * HID + col;
    *(uint32_t*)&Oh[i0] = pack_bf16(o0, o1);
    *(uint32_t*)&Ol[i0] = pack_bf16(o0 - h0, o1 - h1);
    *(uint32_t*)&Oh[i1] = pack_bf16(o2, o3);
    *(uint32_t*)&Ol[i1] = pack_bf16(o2 - h2, o3 - h3);
  }
}

// ---------------------------------------------------------------------------
extern "C" void kernel_launch(void* const* d_in, const int* in_sizes, int n_in,
                              void* d_out, int out_size) {
  const float* queries = (const float*)d_in[0];
  const float* keys    = (const float*)d_in[1];
  const float* values  = (const float*)d_in[2];
  const int*   vlens   = (const int*)d_in[3];
  const float* W[4]    = {(const float*)d_in[4], (const float*)d_in[5],
                          (const float*)d_in[6], (const float*)d_in[7]};
  float* out = (float*)d_out;

  __nv_bfloat16 *whb, *wlb, *qh, *ql, *kh, *kl, *vh, *vl, *oh, *ol;
  cudaGetSymbolAddress((void**)&whb, g_wh);
  cudaGetSymbolAddress((void**)&wlb, g_wl);
  cudaGetSymbolAddress((void**)&qh, g_qh);
  cudaGetSymbolAddress((void**)&ql, g_ql);
  cudaGetSymbolAddress((void**)&kh, g_kh);
  cudaGetSymbolAddress((void**)&kl, g_kl);
  cudaGetSymbolAddress((void**)&vh, g_vh);
  cudaGetSymbolAddress((void**)&vl, g_vl);
  cudaGetSymbolAddress((void**)&oh, g_oh);
  cudaGetSymbolAddress((void**)&ol, g_ol);
  const int WSZ = HID * HID;

  cudaFuncSetAttribute(gemm_tc_hmma<true, true>,
                       cudaFuncAttributeMaxDynamicSharedMemorySize, GEMM_SMEM);
  cudaFuncSetAttribute(gemm_tc_hmma<false, false>,
                       cudaFuncAttributeMaxDynamicSharedMemorySize, GEMM_SMEM);
  cudaFuncSetAttribute(attn_hmma,
                       cudaFuncAttributeMaxDynamicSharedMemorySize, ATTN_SMEM);

  // --- one batched weight split (Wq, Wk, Wv, Wo) ---
  SplitBatch wsb = {};
  for (int i = 0; i < 4; i++) {
    wsb.src[i] = W[i];
    wsb.hi[i] = whb + i * WSZ;
    wsb.lo[i] = wlb + i * WSZ;
  }
  split_batch_kernel<<<dim3(WSZ / 4 / 256, 4), 256>>>(wsb, WSZ / 4);

  // --- Q/K/V projections in ONE launch (grid.z = 3, 768 CTAs) ---
  GemmBatch gp = {};
  gp.af[0] = queries; gp.af[1] = keys; gp.af[2] = values;
  for (int i = 0; i < 3; i++) {
    gp.wh[i] = whb + i * WSZ;
    gp.wl[i] = wlb + i * WSZ;
  }
  gp.ch[0] = qh; gp.cl[0] = ql;
  gp.ch[1] = kh; gp.cl[1] = kl;
  gp.ch[2] = vh; gp.cl[2] = vl;
  gemm_tc_hmma<true, true>
      <<<dim3(HID / 128, M / 128, 3), 256, GEMM_SMEM>>>(gp);

  // --- attention: batch-fastest flattened grid for wave balance ---
  attn_hmma<<<dim3(B * NH, S / 128), 256, ATTN_SMEM>>>(qh, ql, kh, kl, vh, vl,
                                                       vlens, oh, ol);

  // --- output projection (bf16 hi/lo A, fp32 out) ---
  GemmBatch go = {};
  go.ah = oh; go.al = ol;
  go.wh[0] = whb + 3 * WSZ;
  go.wl[0] = wlb + 3 * WSZ;
  go.c = out;
  gemm_tc_hmma<false, false>
      <<<dim3(HID / 128, M / 128, 1), 256, GEMM_SMEM>>>(go);
}

// round 12
// speedup vs baseline: 1.2752x; 1.1290x over previous
#include <cuda_runtime.h>
#include <cuda_bf16.h>
#include <cstdint>

// Problem constants
constexpr int B   = 4;
constexpr int S   = 2048;
constexpr int HID = 512;
constexpr int NH  = 8;
constexpr int DH  = 64;
constexpr int M   = B * S;       // 8192

// Scratch (device globals — no runtime allocation allowed)
__device__ __nv_bfloat16 g_wh[4][HID * HID], g_wl[4][HID * HID];
__device__ __nv_bfloat16 g_qh[M * HID], g_ql[M * HID];
__device__ __nv_bfloat16 g_kh[M * HID], g_kl[M * HID];
__device__ __nv_bfloat16 g_vh[M * HID], g_vl[M * HID];
__device__ __nv_bfloat16 g_oh[M * HID], g_ol[M * HID];

// ---------------------------------------------------------------------------
// mma.sync / ldmatrix / cp.async helpers (plain sm_80+ PTX)
// ---------------------------------------------------------------------------
__device__ __forceinline__ uint32_t smem_u32(const void* p) {
  uint32_t a;
  asm("{ .reg .u64 t; cvta.to.shared.u64 t, %1; cvt.u32.u64 %0, t; }"
      : "=r"(a) : "l"(p));
  return a;
}

#define LDMX4(r0, r1, r2, r3, addr)                                       \
  asm volatile(                                                           \
      "ldmatrix.sync.aligned.m8n8.x4.shared.b16 {%0,%1,%2,%3}, [%4];"     \
      : "=r"(r0), "=r"(r1), "=r"(r2), "=r"(r3) : "r"(addr))

#define LDMX4T(r0, r1, r2, r3, addr)                                      \
  asm volatile(                                                           \
      "ldmatrix.sync.aligned.m8n8.x4.trans.shared.b16 {%0,%1,%2,%3}, [%4];" \
      : "=r"(r0), "=r"(r1), "=r"(r2), "=r"(r3) : "r"(addr))

#define CP_ASYNC16(dst, src)                                              \
  asm volatile("cp.async.cg.shared.global [%0], [%1], 16;" ::             \
                   "r"(dst), "l"(src))
#define CP_COMMIT() asm volatile("cp.async.commit_group;" ::: "memory")
#define CP_WAIT0() asm volatile("cp.async.wait_group 0;" ::: "memory")
#define CP_WAIT1() asm volatile("cp.async.wait_group 1;" ::: "memory")

__device__ __forceinline__ void mma_bf16(float& c0, float& c1, float& c2,
                                         float& c3, uint32_t a0, uint32_t a1,
                                         uint32_t a2, uint32_t a3,
                                         uint32_t b0, uint32_t b1) {
  asm volatile(
      "mma.sync.aligned.m16n8k16.row.col.f32.bf16.bf16.f32 "
      "{%0,%1,%2,%3}, {%4,%5,%6,%7}, {%8,%9}, {%0,%1,%2,%3};"
      : "+f"(c0), "+f"(c1), "+f"(c2), "+f"(c3)
      : "r"(a0), "r"(a1), "r"(a2), "r"(a3), "r"(b0), "r"(b1));
}

__device__ __forceinline__ uint32_t pack_bf16(float a, float b) {
  __nv_bfloat162 t = __floats2bfloat162_rn(a, b);
  return *(uint32_t*)&t;
}

// ---------------------------------------------------------------------------
// fp32 -> (bf16 hi, bf16 lo) split, batched over blockIdx.y (weights).
// ---------------------------------------------------------------------------
struct SplitBatch {
  const float* src[4];
  __nv_bfloat16* hi[4];
  __nv_bfloat16* lo[4];
};

__global__ __launch_bounds__(256) void split_batch_kernel(SplitBatch sb,
                                                          int n4) {
  int i = blockIdx.x * blockDim.x + threadIdx.x;
  if (i >= n4) return;
  int z = blockIdx.y;
  float4 v = ((const float4*)sb.src[z])[i];
  float hx = __bfloat162float(__float2bfloat16(v.x));
  float hy = __bfloat162float(__float2bfloat16(v.y));
  float hz = __bfloat162float(__float2bfloat16(v.z));
  float hw = __bfloat162float(__float2bfloat16(v.w));
  uint2 ho, lw;
  ho.x = pack_bf16(v.x, v.y);
  ho.y = pack_bf16(v.z, v.w);
  lw.x = pack_bf16(v.x - hx, v.y - hy);
  lw.y = pack_bf16(v.z - hz, v.w - hw);
  ((uint2*)sb.hi[z])[i] = ho;
  ((uint2*)sb.lo[z])[i] = lw;
}

// ---------------------------------------------------------------------------
// HMMA bf16x3 GEMM-NT: C = A @ W^T with fp32-equivalent accuracy.
// NEW: for z in {1 (keys), 2 (values)} a CTA whose 128-row m-tile starts at
// s0 >= valid_len[batch] exits immediately — attention never reads K/V rows
// >= ceil64(vlen) <= any 64-aligned s0 >= vlen, so skipped tiles are dead
// work (~47% of K/V projection FLOPs for uniform vlens).
// ---------------------------------------------------------------------------
constexpr int RS = 72;                    // smem row stride in bf16 (144 B)
constexpr int TILE_BYTES = 128 * RS * 2;  // 18432 per tile
constexpr int SA_H = 0;
constexpr int SA_L = TILE_BYTES;
constexpr int SW_BASE = 2 * TILE_BYTES;   // 36864
constexpr int W_STG = 2 * TILE_BYTES;     // Wh+Wl per stage
constexpr int GEMM_SMEM = SW_BASE + 2 * W_STG;  // 110592

struct GemmBatch {
  const float* af[3];                 // AFP32 inputs
  const __nv_bfloat16* ah;            // !AFP32 input (out-proj)
  const __nv_bfloat16* al;
  const __nv_bfloat16* wh[3];
  const __nv_bfloat16* wl[3];
  __nv_bfloat16* ch[3];               // SPLIT outputs
  __nv_bfloat16* cl[3];
  float* c;                           // !SPLIT output
  const int* vlens;                   // valid_lens (skip for z=1,2); null ok
};

template <bool AFP32, bool SPLIT>
__global__ __launch_bounds__(256, 2) void gemm_tc_hmma(GemmBatch p) {
  extern __shared__ __align__(128) char smem[];
  const uint32_t sb = smem_u32(smem);
  const int t = threadIdx.x;
  const int wid = t >> 5, l = t & 31;
  const int wm = wid >> 2;
  const int wn = wid & 3;
  const int m0 = blockIdx.y * 128;
  const int n0 = blockIdx.x * 128;
  const int z = blockIdx.z;

  if (AFP32 && z != 0) {
    // K/V projection: skip m-tiles entirely beyond this batch's valid_len.
    int vl = p.vlens[m0 >> 11];       // batch = m0 / S (S = 2048)
    if ((m0 & (S - 1)) >= vl) return;
  }

  const __nv_bfloat16* Wh = p.wh[z];
  const __nv_bfloat16* Wl = p.wl[z];

  auto issue_w = [&](int stage, int kc) {
    const int koff = kc * 64;
#pragma unroll
    for (int i = 0; i < 8; i++) {
      int idx = t + i * 256;
      int comp = idx >> 10;             // 0: Wh, 1: Wl
      int r = (idx >> 3) & 127;
      int c = idx & 7;
      const __nv_bfloat16* src =
          (comp ? Wl : Wh) + (size_t)(n0 + r) * HID + koff + c * 8;
      uint32_t dst = sb + SW_BASE + stage * W_STG + comp * TILE_BYTES +
                     r * (RS * 2) + c * 16;
      CP_ASYNC16(dst, src);
    }
  };

  issue_w(0, 0);
  CP_COMMIT();

  float acc[4][4][4] = {};

  const int a_row = (l & 15);
  const int a_koff = ((l >> 4) & 1) * 16;
  const int b_row = (l & 7) + ((l >> 4) & 1) * 8;
  const int b_koff = ((l >> 3) & 1) * 16;

  for (int kc = 0; kc < 8; kc++) {
    const int koff = kc * 64;
    if constexpr (AFP32) {
      const float* Af = p.af[z];
#pragma unroll
      for (int i = 0; i < 8; i++) {     // 2048 float4
        int v = t + i * 256;
        int row = v >> 4, c = v & 15;
        float4 fv = *(const float4*)(Af + (size_t)(m0 + row) * HID + koff +
                                     c * 4);
        float hx = __bfloat162float(__float2bfloat16(fv.x));
        float hy = __bfloat162float(__float2bfloat16(fv.y));
        float hz = __bfloat162float(__float2bfloat16(fv.z));
        float hw = __bfloat162float(__float2bfloat16(fv.w));
        uint2 ho, lw;
        ho.x = pack_bf16(fv.x, fv.y);
        ho.y = pack_bf16(fv.z, fv.w);
        lw.x = pack_bf16(fv.x - hx, fv.y - hy);
        lw.y = pack_bf16(fv.z - hz, fv.w - hw);
        uint32_t so = row * (RS * 2) + c * 8;
        *(uint2*)(smem + SA_H + so) = ho;
        *(uint2*)(smem + SA_L + so) = lw;
      }
    } else {
#pragma unroll
      for (int i = 0; i < 8; i++) {     // 2048 x 16B cp.async
        int idx = t + i * 256;
        int comp = idx >> 10;           // 0: Ah, 1: Al
        int r = (idx >> 3) & 127;
        int c = idx & 7;
        const __nv_bfloat16* src =
            (comp ? p.al : p.ah) + (size_t)(m0 + r) * HID + koff + c * 8;
        uint32_t dst = sb + comp * TILE_BYTES + r * (RS * 2) + c * 16;
        CP_ASYNC16(dst, src);
      }
      CP_COMMIT();
    }
    if (kc + 1 < 8) {
      issue_w((kc + 1) & 1, kc + 1);
      CP_COMMIT();
      CP_WAIT1();
    } else {
      CP_WAIT0();
    }
    __syncthreads();
    const uint32_t st_w = sb + SW_BASE + (kc & 1) * W_STG;

#pragma unroll
    for (int ks = 0; ks < 4; ks++) {
      const int kb = ks * 32;
      uint32_t ah[4][4], al[4][4], bh[8], bl[8];
#pragma unroll
      for (int mt = 0; mt < 4; mt++) {
        uint32_t ra = (wm * 64 + mt * 16 + a_row) * (RS * 2) + kb + a_koff;
        LDMX4(ah[mt][0], ah[mt][1], ah[mt][2], ah[mt][3], sb + SA_H + ra);
        LDMX4(al[mt][0], al[mt][1], al[mt][2], al[mt][3], sb + SA_L + ra);
      }
#pragma unroll
      for (int np = 0; np < 2; np++) {
        uint32_t rb = (wn * 32 + np * 16 + b_row) * (RS * 2) + kb + b_koff;
        LDMX4(bh[np * 4 + 0], bh[np * 4 + 1], bh[np * 4 + 2], bh[np * 4 + 3],
              st_w + rb);
        LDMX4(bl[np * 4 + 0], bl[np * 4 + 1], bl[np * 4 + 2], bl[np * 4 + 3],
              st_w + TILE_BYTES + rb);
      }
#pragma unroll
      for (int mt = 0; mt < 4; mt++)
#pragma unroll
        for (int nt = 0; nt < 4; nt++) {
          float* c = acc[mt][nt];
          mma_bf16(c[0], c[1], c[2], c[3], ah[mt][0], ah[mt][1], ah[mt][2],
                   ah[mt][3], bh[nt * 2], bh[nt * 2 + 1]);
          mma_bf16(c[0], c[1], c[2], c[3], ah[mt][0], ah[mt][1], ah[mt][2],
                   ah[mt][3], bl[nt * 2], bl[nt * 2 + 1]);
          mma_bf16(c[0], c[1], c[2], c[3], al[mt][0], al[mt][1], al[mt][2],
                   al[mt][3], bh[nt * 2], bh[nt * 2 + 1]);
        }
    }
    __syncthreads();
  }

  const int er = l >> 2, ec = (l & 3) * 2;
#pragma unroll
  for (int mt = 0; mt < 4; mt++) {
    int row = m0 + wm * 64 + mt * 16 + er;
#pragma unroll
    for (int nt = 0; nt < 4; nt++) {
      int col = n0 + wn * 32 + nt * 8 + ec;
      float* a = acc[mt][nt];
      if constexpr (SPLIT) {
        float h0 = __bfloat162float(__float2bfloat16(a[0]));
        float h1 = __bfloat162float(__float2bfloat16(a[1]));
        float h2 = __bfloat162float(__float2bfloat16(a[2]));
        float h3 = __bfloat162float(__float2bfloat16(a[3]));
        size_t i0 = (size_t)row * HID + col;
        size_t i1 = (size_t)(row + 8) * HID + col;
        *(uint32_t*)&p.ch[z][i0] = pack_bf16(a[0], a[1]);
        *(uint32_t*)&p.cl[z][i0] = pack_bf16(a[0] - h0, a[1] - h1);
        *(uint32_t*)&p.ch[z][i1] = pack_bf16(a[2], a[3]);
        *(uint32_t*)&p.cl[z][i1] = pack_bf16(a[2] - h2, a[3] - h3);
      } else {
        *(float2*)&p.c[(size_t)row * HID + col] = make_float2(a[0], a[1]);
        *(float2*)&p.c[(size_t)(row + 8) * HID + col] =
            make_float2(a[2], a[3]);
      }
    }
  }
}

// ---------------------------------------------------------------------------
// HMMA flash attention (bf16x3, exp2-domain softmax). Round-9 grid layout
// (qt, h, b) — the round-11 batch-fastest flattening regressed.
// ---------------------------------------------------------------------------
constexpr float SC2 = 0.125f * 1.4426950408889634f;  // (1/8)*log2(e)

constexpr int AQ_H = 0;
constexpr int AQ_L = 128 * RS * 2;
constexpr int STG0 = 2 * 128 * RS * 2;         // 36864
constexpr int KV_COMP = 64 * RS * 2;           // 9216
constexpr int STG_SZ = 4 * KV_COMP;            // 36864
constexpr int ATTN_SMEM = STG0 + 2 * STG_SZ;   // 110592

__global__ __launch_bounds__(256, 2) void attn_hmma(
    const __nv_bfloat16* __restrict__ Qh, const __nv_bfloat16* __restrict__ Ql,
    const __nv_bfloat16* __restrict__ Kh, const __nv_bfloat16* __restrict__ Kl,
    const __nv_bfloat16* __restrict__ Vh, const __nv_bfloat16* __restrict__ Vl,
    const int* __restrict__ valid_lens, __nv_bfloat16* __restrict__ Oh,
    __nv_bfloat16* __restrict__ Ol) {
  extern __shared__ __align__(128) char smem[];
  const uint32_t sb = smem_u32(smem);
  const int qt = blockIdx.x, h = blockIdx.y, b = blockIdx.z;
  const int t = threadIdx.x;
  const int wid = t >> 5, l = t & 31;
  const int q0 = qt * 128;
  const int vlen = valid_lens[b];
  const int ntiles = (vlen + 63) >> 6;

  const __nv_bfloat16* kv_src[4] = {Kh, Kl, Vh, Vl};

  auto issue_tile = [&](int stage, int kbase) {
#pragma unroll
    for (int i = 0; i < 8; i++) {
      int idx = t + i * 256;
      int comp = idx >> 9;
      int r = (idx >> 3) & 63;
      int c = idx & 7;
      const __nv_bfloat16* src =
          kv_src[comp] + (size_t)(b * S + kbase + r) * HID + h * DH + c * 8;
      uint32_t dst =
          sb + STG0 + stage * STG_SZ + comp * KV_COMP + r * (RS * 2) + c * 16;
      CP_ASYNC16(dst, src);
    }
  };

  issue_tile(0, 0);
  CP_COMMIT();
#pragma unroll
  for (int i = 0; i < 4; i++) {
    int v = t + i * 256;
    int row = v >> 3, c = v & 7;
    size_t g = (size_t)(b * S + q0 + row) * HID + h * DH + c * 8;
    uint32_t so = row * (RS * 2) + c * 16;
    *(uint4*)(smem + AQ_H + so) = *(const uint4*)(Qh + g);
    *(uint4*)(smem + AQ_L + so) = *(const uint4*)(Ql + g);
  }
  __syncthreads();

  const int a_row = (l & 15);
  const int a_koff = ((l >> 4) & 1) * 16;
  const int b_row = (l & 7) + ((l >> 4) & 1) * 8;
  const int b_koff = ((l >> 3) & 1) * 16;
  const int v_row = (l & 7) + ((l >> 3) & 1) * 8;
  const int v_col = ((l >> 4) & 1) * 16;
  const int cb = (l & 3) * 2;

  uint32_t qh[4][4], ql[4][4];
#pragma unroll
  for (int ks = 0; ks < 4; ks++) {
    uint32_t ra = (wid * 16 + a_row) * (RS * 2) + ks * 32 + a_koff;
    LDMX4(qh[ks][0], qh[ks][1], qh[ks][2], qh[ks][3], sb + AQ_H + ra);
    LDMX4(ql[ks][0], ql[ks][1], ql[ks][2], ql[ks][3], sb + AQ_L + ra);
  }

  float oacc[8][4] = {};
  float m0r = -1e30f, m1r = -1e30f, l0r = 0.f, l1r = 0.f;

  for (int kt = 0; kt < ntiles; kt++) {
    const int kbase = kt * 64;
    const uint32_t kb_h = sb + STG0 + (kt & 1) * STG_SZ;
    const uint32_t kb_l = kb_h + KV_COMP;
    const uint32_t vb_h = kb_h + 2 * KV_COMP;
    const uint32_t vb_l = kb_h + 3 * KV_COMP;

    CP_WAIT0();
    __syncthreads();
    if (kt + 1 < ntiles) {
      issue_tile((kt + 1) & 1, kbase + 64);
      CP_COMMIT();
    }

    float sc[8][4];
#pragma unroll
    for (int nt = 0; nt < 8; nt++)
#pragma unroll
      for (int c = 0; c < 4; c++) sc[nt][c] = 0.f;
#pragma unroll
    for (int ks = 0; ks < 4; ks++) {
      uint32_t khf[16], klf[16];
#pragma unroll
      for (int np = 0; np < 4; np++) {
        uint32_t rb = (np * 16 + b_row) * (RS * 2) + ks * 32 + b_koff;
        LDMX4(khf[np * 4 + 0], khf[np * 4 + 1], khf[np * 4 + 2],
              khf[np * 4 + 3], kb_h + rb);
        LDMX4(klf[np * 4 + 0], klf[np * 4 + 1], klf[np * 4 + 2],
              klf[np * 4 + 3], kb_l + rb);
      }
#pragma unroll
      for (int nt = 0; nt < 8; nt++) {
        float* c = sc[nt];
        mma_bf16(c[0], c[1], c[2], c[3], qh[ks][0], qh[ks][1], qh[ks][2],
                 qh[ks][3], khf[nt * 2], khf[nt * 2 + 1]);
        mma_bf16(c[0], c[1], c[2], c[3], qh[ks][0], qh[ks][1], qh[ks][2],
                 qh[ks][3], klf[nt * 2], klf[nt * 2 + 1]);
        mma_bf16(c[0], c[1], c[2], c[3], ql[ks][0], ql[ks][1], ql[ks][2],
                 ql[ks][3], khf[nt * 2], khf[nt * 2 + 1]);
      }
    }

#pragma unroll
    for (int nt = 0; nt < 8; nt++)
#pragma unroll
      for (int c = 0; c < 4; c++) sc[nt][c] *= SC2;
    if (kbase + 64 > vlen) {
#pragma unroll
      for (int nt = 0; nt < 8; nt++) {
        int k0 = kbase + nt * 8 + cb;
        if (k0 >= vlen) { sc[nt][0] = -1e30f; sc[nt][2] = -1e30f; }
        if (k0 + 1 >= vlen) { sc[nt][1] = -1e30f; sc[nt][3] = -1e30f; }
      }
    }

    float rm0 = -1e30f, rm1 = -1e30f;
#pragma unroll
    for (int nt = 0; nt < 8; nt++) {
      rm0 = fmaxf(rm0, fmaxf(sc[nt][0], sc[nt][1]));
      rm1 = fmaxf(rm1, fmaxf(sc[nt][2], sc[nt][3]));
    }
    rm0 = fmaxf(rm0, __shfl_xor_sync(0xffffffffu, rm0, 1));
    rm0 = fmaxf(rm0, __shfl_xor_sync(0xffffffffu, rm0, 2));
    rm1 = fmaxf(rm1, __shfl_xor_sync(0xffffffffu, rm1, 1));
    rm1 = fmaxf(rm1, __shfl_xor_sync(0xffffffffu, rm1, 2));
    float mn0 = fmaxf(m0r, rm0), mn1 = fmaxf(m1r, rm1);
    float corr0 = exp2f(m0r - mn0), corr1 = exp2f(m1r - mn1);

    uint32_t ph[8][2], pl[8][2];
    float rs0 = 0.f, rs1 = 0.f;
#pragma unroll
    for (int nt = 0; nt < 8; nt++) {
      float p0 = exp2f(sc[nt][0] - mn0);
      float p1 = exp2f(sc[nt][1] - mn0);
      float p2 = exp2f(sc[nt][2] - mn1);
      float p3 = exp2f(sc[nt][3] - mn1);
      rs0 += p0 + p1;
      rs1 += p2 + p3;
      float h0 = __bfloat162float(__float2bfloat16(p0));
      float h1 = __bfloat162float(__float2bfloat16(p1));
      float h2 = __bfloat162float(__float2bfloat16(p2));
      float h3 = __bfloat162float(__float2bfloat16(p3));
      ph[nt][0] = pack_bf16(p0, p1);
      ph[nt][1] = pack_bf16(p2, p3);
      pl[nt][0] = pack_bf16(p0 - h0, p1 - h1);
      pl[nt][1] = pack_bf16(p2 - h2, p3 - h3);
    }
    rs0 += __shfl_xor_sync(0xffffffffu, rs0, 1);
    rs0 += __shfl_xor_sync(0xffffffffu, rs0, 2);
    rs1 += __shfl_xor_sync(0xffffffffu, rs1, 1);
    rs1 += __shfl_xor_sync(0xffffffffu, rs1, 2);
    l0r = l0r * corr0 + rs0;
    l1r = l1r * corr1 + rs1;
    m0r = mn0;
    m1r = mn1;
#pragma unroll
    for (int nt = 0; nt < 8; nt++) {
      oacc[nt][0] *= corr0;
      oacc[nt][1] *= corr0;
      oacc[nt][2] *= corr1;
      oacc[nt][3] *= corr1;
    }

#pragma unroll
    for (int ks = 0; ks < 4; ks++) {
      uint32_t vhf[16], vlf[16];
#pragma unroll
      for (int np = 0; np < 4; np++) {
        uint32_t rv = (ks * 16 + v_row) * (RS * 2) + np * 32 + v_col;
        LDMX4T(vhf[np * 4 + 0], vhf[np * 4 + 1], vhf[np * 4 + 2],
               vhf[np * 4 + 3], vb_h + rv);
        LDMX4T(vlf[np * 4 + 0], vlf[np * 4 + 1], vlf[np * 4 + 2],
               vlf[np * 4 + 3], vb_l + rv);
      }
      uint32_t a0 = ph[2 * ks][0], a1 = ph[2 * ks][1];
      uint32_t a2 = ph[2 * ks + 1][0], a3 = ph[2 * ks + 1][1];
      uint32_t e0 = pl[2 * ks][0], e1 = pl[2 * ks][1];
      uint32_t e2 = pl[2 * ks + 1][0], e3 = pl[2 * ks + 1][1];
#pragma unroll
      for (int nt = 0; nt < 8; nt++) {
        float* c = oacc[nt];
        mma_bf16(c[0], c[1], c[2], c[3], a0, a1, a2, a3, vhf[nt * 2],
                 vhf[nt * 2 + 1]);
        mma_bf16(c[0], c[1], c[2], c[3], a0, a1, a2, a3, vlf[nt * 2],
                 vlf[nt * 2 + 1]);
        mma_bf16(c[0], c[1], c[2], c[3], e0, e1, e2, e3, vhf[nt * 2],
                 vhf[nt * 2 + 1]);
      }
    }
  }

  float inv0 = 1.f / l0r, inv1 = 1.f / l1r;
  int r0 = q0 + wid * 16 + (l >> 2);
#pragma unroll
  for (int nt = 0; nt < 8; nt++) {
    int col = h * DH + nt * 8 + cb;
    float o0 = oacc[nt][0] * inv0, o1 = oacc[nt][1] * inv0;
    float o2 = oacc[nt][2] * inv1, o3 = oacc[nt][3] * inv1;
    float h0 = __bfloat162float(__float2bfloat16(o0));
    float h1 = __bfloat162float(__float2bfloat16(o1));
    float h2 = __bfloat162float(__float2bfloat16(o2));
    float h3 = __bfloat162float(__float2bfloat16(o3));
    size_t i0 = (size_t)(b * S + r0) * HID + col;
    size_t i1 = (size_t)(b * S + r0 + 8) * HID + col;
    *(uint32_t*)&Oh[i0] = pack_bf16(o0, o1);
    *(uint32_t*)&Ol[i0] = pack_bf16(o0 - h0, o1 - h1);
    *(uint32_t*)&Oh[i1] = pack_bf16(o2, o3);
    *(uint32_t*)&Ol[i1] = pack_bf16(o2 - h2, o3 - h3);
  }
}

// ---------------------------------------------------------------------------
extern "C" void kernel_launch(void* const* d_in, const int* in_sizes, int n_in,
                              void* d_out, int out_size) {
  const float* queries = (const float*)d_in[0];
  const float* keys    = (const float*)d_in[1];
  const float* values  = (const float*)d_in[2];
  const int*   vlens   = (const int*)d_in[3];
  const float* W[4]    = {(const float*)d_in[4], (const float*)d_in[5],
                          (const float*)d_in[6], (const float*)d_in[7]};
  float* out = (float*)d_out;

  __nv_bfloat16 *whb, *wlb, *qh, *ql, *kh, *kl, *vh, *vl, *oh, *ol;
  cudaGetSymbolAddress((void**)&whb, g_wh);
  cudaGetSymbolAddress((void**)&wlb, g_wl);
  cudaGetSymbolAddress((void**)&qh, g_qh);
  cudaGetSymbolAddress((void**)&ql, g_ql);
  cudaGetSymbolAddress((void**)&kh, g_kh);
  cudaGetSymbolAddress((void**)&kl, g_kl);
  cudaGetSymbolAddress((void**)&vh, g_vh);
  cudaGetSymbolAddress((void**)&vl, g_vl);
  cudaGetSymbolAddress((void**)&oh, g_oh);
  cudaGetSymbolAddress((void**)&ol, g_ol);
  const int WSZ = HID * HID;

  cudaFuncSetAttribute(gemm_tc_hmma<true, true>,
                       cudaFuncAttributeMaxDynamicSharedMemorySize, GEMM_SMEM);
  cudaFuncSetAttribute(gemm_tc_hmma<false, false>,
                       cudaFuncAttributeMaxDynamicSharedMemorySize, GEMM_SMEM);
  cudaFuncSetAttribute(attn_hmma,
                       cudaFuncAttributeMaxDynamicSharedMemorySize, ATTN_SMEM);

  // --- one batched weight split (Wq, Wk, Wv, Wo) ---
  SplitBatch wsb = {};
  for (int i = 0; i < 4; i++) {
    wsb.src[i] = W[i];
    wsb.hi[i] = whb + i * WSZ;
    wsb.lo[i] = wlb + i * WSZ;
  }
  split_batch_kernel<<<dim3(WSZ / 4 / 256, 4), 256>>>(wsb, WSZ / 4);

  // --- Q/K/V projections in ONE launch; K/V tiles beyond valid_len skipped ---
  GemmBatch gp = {};
  gp.af[0] = queries; gp.af[1] = keys; gp.af[2] = values;
  for (int i = 0; i < 3; i++) {
    gp.wh[i] = whb + i * WSZ;
    gp.wl[i] = wlb + i * WSZ;
  }
  gp.ch[0] = qh; gp.cl[0] = ql;
  gp.ch[1] = kh; gp.cl[1] = kl;
  gp.ch[2] = vh; gp.cl[2] = vl;
  gp.vlens = vlens;
  gemm_tc_hmma<true, true>
      <<<dim3(HID / 128, M / 128, 3), 256, GEMM_SMEM>>>(gp);

  // --- attention (round-9 grid layout) ---
  attn_hmma<<<dim3(S / 128, NH, B), 256, ATTN_SMEM>>>(qh, ql, kh, kl, vh, vl,
                                                      vlens, oh, ol);

  // --- output projection (bf16 hi/lo A, fp32 out) ---
  GemmBatch go = {};
  go.ah = oh; go.al = ol;
  go.wh[0] = whb + 3 * WSZ;
  go.wl[0] = wlb + 3 * WSZ;
  go.c = out;
  go.vlens = nullptr;
  gemm_tc_hmma<false, false>
      <<<dim3(HID / 128, M / 128, 1), 256, GEMM_SMEM>>>(go);
}

// round 13
// speedup vs baseline: 1.6654x; 1.3060x over previous
#include <cuda_runtime.h>
#include <cuda_bf16.h>
#include <cuda_fp16.h>
#include <cstdint>

// Problem constants
constexpr int B   = 4;
constexpr int S   = 2048;
constexpr int HID = 512;
constexpr int NH  = 8;
constexpr int DH  = 64;
constexpr int M   = B * S;       // 8192

// Scratch (device globals — no runtime allocation allowed)
__device__ __nv_bfloat16 g_wh[4][HID * HID], g_wl[4][HID * HID];
__device__ __half g_q16[M * HID], g_k16[M * HID], g_v16[M * HID];
__device__ __nv_bfloat16 g_oh[M * HID], g_ol[M * HID];

// ---------------------------------------------------------------------------
// mma.sync / ldmatrix / cp.async helpers (plain sm_80+ PTX)
// ---------------------------------------------------------------------------
__device__ __forceinline__ uint32_t smem_u32(const void* p) {
  uint32_t a;
  asm("{ .reg .u64 t; cvta.to.shared.u64 t, %1; cvt.u32.u64 %0, t; }"
      : "=r"(a) : "l"(p));
  return a;
}

#define LDMX4(r0, r1, r2, r3, addr)                                       \
  asm volatile(                                                           \
      "ldmatrix.sync.aligned.m8n8.x4.shared.b16 {%0,%1,%2,%3}, [%4];"     \
      : "=r"(r0), "=r"(r1), "=r"(r2), "=r"(r3) : "r"(addr))

#define LDMX4T(r0, r1, r2, r3, addr)                                      \
  asm volatile(                                                           \
      "ldmatrix.sync.aligned.m8n8.x4.trans.shared.b16 {%0,%1,%2,%3}, [%4];" \
      : "=r"(r0), "=r"(r1), "=r"(r2), "=r"(r3) : "r"(addr))

#define CP_ASYNC16(dst, src)                                              \
  asm volatile("cp.async.cg.shared.global [%0], [%1], 16;" ::             \
                   "r"(dst), "l"(src))
#define CP_COMMIT() asm volatile("cp.async.commit_group;" ::: "memory")
#define CP_WAIT0() asm volatile("cp.async.wait_group 0;" ::: "memory")
#define CP_WAIT1() asm volatile("cp.async.wait_group 1;" ::: "memory")

__device__ __forceinline__ void mma_bf16(float& c0, float& c1, float& c2,
                                         float& c3, uint32_t a0, uint32_t a1,
                                         uint32_t a2, uint32_t a3,
                                         uint32_t b0, uint32_t b1) {
  asm volatile(
      "mma.sync.aligned.m16n8k16.row.col.f32.bf16.bf16.f32 "
      "{%0,%1,%2,%3}, {%4,%5,%6,%7}, {%8,%9}, {%0,%1,%2,%3};"
      : "+f"(c0), "+f"(c1), "+f"(c2), "+f"(c3)
      : "r"(a0), "r"(a1), "r"(a2), "r"(a3), "r"(b0), "r"(b1));
}

__device__ __forceinline__ void mma_f16(float& c0, float& c1, float& c2,
                                        float& c3, uint32_t a0, uint32_t a1,
                                        uint32_t a2, uint32_t a3,
                                        uint32_t b0, uint32_t b1) {
  asm volatile(
      "mma.sync.aligned.m16n8k16.row.col.f32.f16.f16.f32 "
      "{%0,%1,%2,%3}, {%4,%5,%6,%7}, {%8,%9}, {%0,%1,%2,%3};"
      : "+f"(c0), "+f"(c1), "+f"(c2), "+f"(c3)
      : "r"(a0), "r"(a1), "r"(a2), "r"(a3), "r"(b0), "r"(b1));
}

__device__ __forceinline__ uint32_t pack_bf16(float a, float b) {
  __nv_bfloat162 t = __floats2bfloat162_rn(a, b);
  return *(uint32_t*)&t;
}
__device__ __forceinline__ uint32_t pack_f16(float a, float b) {
  __half2 t = __floats2half2_rn(a, b);
  return *(uint32_t*)&t;
}

// ---------------------------------------------------------------------------
// fp32 -> (bf16 hi, bf16 lo) split, batched over blockIdx.y (weights).
// ---------------------------------------------------------------------------
struct SplitBatch {
  const float* src[4];
  __nv_bfloat16* hi[4];
  __nv_bfloat16* lo[4];
};

__global__ __launch_bounds__(256) void split_batch_kernel(SplitBatch sb,
                                                          int n4) {
  int i = blockIdx.x * blockDim.x + threadIdx.x;
  if (i >= n4) return;
  int z = blockIdx.y;
  float4 v = ((const float4*)sb.src[z])[i];
  float hx = __bfloat162float(__float2bfloat16(v.x));
  float hy = __bfloat162float(__float2bfloat16(v.y));
  float hz = __bfloat162float(__float2bfloat16(v.z));
  float hw = __bfloat162float(__float2bfloat16(v.w));
  uint2 ho, lw;
  ho.x = pack_bf16(v.x, v.y);
  ho.y = pack_bf16(v.z, v.w);
  lw.x = pack_bf16(v.x - hx, v.y - hy);
  lw.y = pack_bf16(v.z - hz, v.w - hw);
  ((uint2*)sb.hi[z])[i] = ho;
  ((uint2*)sb.lo[z])[i] = lw;
}

// ---------------------------------------------------------------------------
// HMMA bf16x3 GEMM-NT: C = A @ W^T with fp32-equivalent accuracy.
// QKV (F16OUT): emits fp16 single-precision outputs for the fp16 attention.
// Out-proj (!F16OUT): reads bf16 hi/lo A (attention output), fp32 C.
// K/V m-tiles beyond valid_len are skipped (attention never reads them).
// ---------------------------------------------------------------------------
constexpr int RS = 72;                    // smem row stride in bf16 (144 B)
constexpr int TILE_BYTES = 128 * RS * 2;  // 18432 per tile
constexpr int SA_H = 0;
constexpr int SA_L = TILE_BYTES;
constexpr int SW_BASE = 2 * TILE_BYTES;   // 36864
constexpr int W_STG = 2 * TILE_BYTES;     // Wh+Wl per stage
constexpr int GEMM_SMEM = SW_BASE + 2 * W_STG;  // 110592

struct GemmBatch {
  const float* af[3];                 // AFP32 inputs
  const __nv_bfloat16* ah;            // !AFP32 input (out-proj)
  const __nv_bfloat16* al;
  const __nv_bfloat16* wh[3];
  const __nv_bfloat16* wl[3];
  __half* c16[3];                     // F16OUT outputs
  float* c;                           // !F16OUT output
  const int* vlens;                   // valid_lens (skip for z=1,2); null ok
};

template <bool AFP32, bool F16OUT>
__global__ __launch_bounds__(256, 2) void gemm_tc_hmma(GemmBatch p) {
  extern __shared__ __align__(128) char smem[];
  const uint32_t sb = smem_u32(smem);
  const int t = threadIdx.x;
  const int wid = t >> 5, l = t & 31;
  const int wm = wid >> 2;
  const int wn = wid & 3;
  const int m0 = blockIdx.y * 128;
  const int n0 = blockIdx.x * 128;
  const int z = blockIdx.z;

  if (AFP32 && z != 0) {
    int vl = p.vlens[m0 >> 11];       // batch = m0 / S (S = 2048)
    if ((m0 & (S - 1)) >= vl) return;
  }

  const __nv_bfloat16* Wh = p.wh[z];
  const __nv_bfloat16* Wl = p.wl[z];

  auto issue_w = [&](int stage, int kc) {
    const int koff = kc * 64;
#pragma unroll
    for (int i = 0; i < 8; i++) {
      int idx = t + i * 256;
      int comp = idx >> 10;             // 0: Wh, 1: Wl
      int r = (idx >> 3) & 127;
      int c = idx & 7;
      const __nv_bfloat16* src =
          (comp ? Wl : Wh) + (size_t)(n0 + r) * HID + koff + c * 8;
      uint32_t dst = sb + SW_BASE + stage * W_STG + comp * TILE_BYTES +
                     r * (RS * 2) + c * 16;
      CP_ASYNC16(dst, src);
    }
  };

  issue_w(0, 0);
  CP_COMMIT();

  float acc[4][4][4] = {};

  const int a_row = (l & 15);
  const int a_koff = ((l >> 4) & 1) * 16;
  const int b_row = (l & 7) + ((l >> 4) & 1) * 8;
  const int b_koff = ((l >> 3) & 1) * 16;

  for (int kc = 0; kc < 8; kc++) {
    const int koff = kc * 64;
    if constexpr (AFP32) {
      const float* Af = p.af[z];
#pragma unroll
      for (int i = 0; i < 8; i++) {     // 2048 float4
        int v = t + i * 256;
        int row = v >> 4, c = v & 15;
        float4 fv = *(const float4*)(Af + (size_t)(m0 + row) * HID + koff +
                                     c * 4);
        float hx = __bfloat162float(__float2bfloat16(fv.x));
        float hy = __bfloat162float(__float2bfloat16(fv.y));
        float hz = __bfloat162float(__float2bfloat16(fv.z));
        float hw = __bfloat162float(__float2bfloat16(fv.w));
        uint2 ho, lw;
        ho.x = pack_bf16(fv.x, fv.y);
        ho.y = pack_bf16(fv.z, fv.w);
        lw.x = pack_bf16(fv.x - hx, fv.y - hy);
        lw.y = pack_bf16(fv.z - hz, fv.w - hw);
        uint32_t so = row * (RS * 2) + c * 8;
        *(uint2*)(smem + SA_H + so) = ho;
        *(uint2*)(smem + SA_L + so) = lw;
      }
    } else {
#pragma unroll
      for (int i = 0; i < 8; i++) {     // 2048 x 16B cp.async
        int idx = t + i * 256;
        int comp = idx >> 10;           // 0: Ah, 1: Al
        int r = (idx >> 3) & 127;
        int c = idx & 7;
        const __nv_bfloat16* src =
            (comp ? p.al : p.ah) + (size_t)(m0 + r) * HID + koff + c * 8;
        uint32_t dst = sb + comp * TILE_BYTES + r * (RS * 2) + c * 16;
        CP_ASYNC16(dst, src);
      }
      CP_COMMIT();
    }
    if (kc + 1 < 8) {
      issue_w((kc + 1) & 1, kc + 1);
      CP_COMMIT();
      CP_WAIT1();
    } else {
      CP_WAIT0();
    }
    __syncthreads();
    const uint32_t st_w = sb + SW_BASE + (kc & 1) * W_STG;

#pragma unroll
    for (int ks = 0; ks < 4; ks++) {
      const int kb = ks * 32;
      uint32_t ah[4][4], al[4][4], bh[8], bl[8];
#pragma unroll
      for (int mt = 0; mt < 4; mt++) {
        uint32_t ra = (wm * 64 + mt * 16 + a_row) * (RS * 2) + kb + a_koff;
        LDMX4(ah[mt][0], ah[mt][1], ah[mt][2], ah[mt][3], sb + SA_H + ra);
        LDMX4(al[mt][0], al[mt][1], al[mt][2], al[mt][3], sb + SA_L + ra);
      }
#pragma unroll
      for (int np = 0; np < 2; np++) {
        uint32_t rb = (wn * 32 + np * 16 + b_row) * (RS * 2) + kb + b_koff;
        LDMX4(bh[np * 4 + 0], bh[np * 4 + 1], bh[np * 4 + 2], bh[np * 4 + 3],
              st_w + rb);
        LDMX4(bl[np * 4 + 0], bl[np * 4 + 1], bl[np * 4 + 2], bl[np * 4 + 3],
              st_w + TILE_BYTES + rb);
      }
#pragma unroll
      for (int mt = 0; mt < 4; mt++)
#pragma unroll
        for (int nt = 0; nt < 4; nt++) {
          float* c = acc[mt][nt];
          mma_bf16(c[0], c[1], c[2], c[3], ah[mt][0], ah[mt][1], ah[mt][2],
                   ah[mt][3], bh[nt * 2], bh[nt * 2 + 1]);
          mma_bf16(c[0], c[1], c[2], c[3], ah[mt][0], ah[mt][1], ah[mt][2],
                   ah[mt][3], bl[nt * 2], bl[nt * 2 + 1]);
          mma_bf16(c[0], c[1], c[2], c[3], al[mt][0], al[mt][1], al[mt][2],
                   al[mt][3], bh[nt * 2], bh[nt * 2 + 1]);
        }
    }
    __syncthreads();
  }

  const int er = l >> 2, ec = (l & 3) * 2;
#pragma unroll
  for (int mt = 0; mt < 4; mt++) {
    int row = m0 + wm * 64 + mt * 16 + er;
#pragma unroll
    for (int nt = 0; nt < 4; nt++) {
      int col = n0 + wn * 32 + nt * 8 + ec;
      float* a = acc[mt][nt];
      if constexpr (F16OUT) {
        size_t i0 = (size_t)row * HID + col;
        size_t i1 = (size_t)(row + 8) * HID + col;
        *(uint32_t*)&p.c16[z][i0] = pack_f16(a[0], a[1]);
        *(uint32_t*)&p.c16[z][i1] = pack_f16(a[2], a[3]);
      } else {
        *(float2*)&p.c[(size_t)row * HID + col] = make_float2(a[0], a[1]);
        *(float2*)&p.c[(size_t)(row + 8) * HID + col] =
            make_float2(a[2], a[3]);
      }
    }
  }
}

// ---------------------------------------------------------------------------
// fp16 flash attention (single-term QK and PV — fp16's 10 mantissa bits give
// ~4e-4 output error vs bf16x3's 1e-5, at 3x fewer tensor-pipe slots).
// fp32 accumulate + fp32 exp2-domain softmax. Q/K/V read as fp16; output
// emitted as bf16 hi/lo for the bf16x3 out-projection.
// ---------------------------------------------------------------------------
constexpr float SC2 = 0.125f * 1.4426950408889634f;  // (1/8)*log2(e)

constexpr int AQ16 = 0;                        // Q fp16: 128 x 144B
constexpr int ASTG0 = 128 * RS * 2;            // 18432
constexpr int AKV_COMP = 64 * RS * 2;          // 9216 (K or V per stage)
constexpr int ASTG_SZ = 2 * AKV_COMP;          // 18432
constexpr int ATTN_SMEM = ASTG0 + 2 * ASTG_SZ; // 55296

__global__ __launch_bounds__(256, 2) void attn_hmma(
    const __half* __restrict__ Q16, const __half* __restrict__ K16,
    const __half* __restrict__ V16, const int* __restrict__ valid_lens,
    __nv_bfloat16* __restrict__ Oh, __nv_bfloat16* __restrict__ Ol) {
  extern __shared__ __align__(128) char smem[];
  const uint32_t sb = smem_u32(smem);
  const int qt = blockIdx.x, h = blockIdx.y, b = blockIdx.z;
  const int t = threadIdx.x;
  const int wid = t >> 5, l = t & 31;
  const int q0 = qt * 128;
  const int vlen = valid_lens[b];
  const int ntiles = (vlen + 63) >> 6;

  auto issue_tile = [&](int stage, int kbase) {
#pragma unroll
    for (int i = 0; i < 4; i++) {       // 1024 x 16B cp.async
      int idx = t + i * 256;
      int comp = idx >> 9;              // 0: K, 1: V
      int r = (idx >> 3) & 63;
      int c = idx & 7;
      const __half* src =
          (comp ? V16 : K16) + (size_t)(b * S + kbase + r) * HID + h * DH +
          c * 8;
      uint32_t dst = sb + ASTG0 + stage * ASTG_SZ + comp * AKV_COMP +
                     r * (RS * 2) + c * 16;
      CP_ASYNC16(dst, src);
    }
  };

  issue_tile(0, 0);
  CP_COMMIT();
#pragma unroll
  for (int i = 0; i < 4; i++) {         // Q tile: 1024 x 16B
    int v = t + i * 256;
    int row = v >> 3, c = v & 7;
    size_t g = (size_t)(b * S + q0 + row) * HID + h * DH + c * 8;
    *(uint4*)(smem + AQ16 + row * (RS * 2) + c * 16) =
        *(const uint4*)(Q16 + g);
  }
  __syncthreads();

  const int a_row = (l & 15);
  const int a_koff = ((l >> 4) & 1) * 16;
  const int b_row = (l & 7) + ((l >> 4) & 1) * 8;
  const int b_koff = ((l >> 3) & 1) * 16;
  const int v_row = (l & 7) + ((l >> 3) & 1) * 8;
  const int v_col = ((l >> 4) & 1) * 16;
  const int cb = (l & 3) * 2;

  uint32_t qf[4][4];
#pragma unroll
  for (int ks = 0; ks < 4; ks++) {
    uint32_t ra = (wid * 16 + a_row) * (RS * 2) + ks * 32 + a_koff;
    LDMX4(qf[ks][0], qf[ks][1], qf[ks][2], qf[ks][3], sb + AQ16 + ra);
  }

  float oacc[8][4] = {};
  float m0r = -1e30f, m1r = -1e30f, l0r = 0.f, l1r = 0.f;

  for (int kt = 0; kt < ntiles; kt++) {
    const int kbase = kt * 64;
    const uint32_t kb16 = sb + ASTG0 + (kt & 1) * ASTG_SZ;
    const uint32_t vb16 = kb16 + AKV_COMP;

    CP_WAIT0();
    __syncthreads();
    if (kt + 1 < ntiles) {
      issue_tile((kt + 1) & 1, kbase + 64);
      CP_COMMIT();
    }

    // --- scores = Q K^T (fp16 single term) ---
    float sc[8][4];
#pragma unroll
    for (int nt = 0; nt < 8; nt++)
#pragma unroll
      for (int c = 0; c < 4; c++) sc[nt][c] = 0.f;
#pragma unroll
    for (int ks = 0; ks < 4; ks++) {
      uint32_t kf[16];
#pragma unroll
      for (int np = 0; np < 4; np++) {
        uint32_t rb = (np * 16 + b_row) * (RS * 2) + ks * 32 + b_koff;
        LDMX4(kf[np * 4 + 0], kf[np * 4 + 1], kf[np * 4 + 2], kf[np * 4 + 3],
              kb16 + rb);
      }
#pragma unroll
      for (int nt = 0; nt < 8; nt++) {
        float* c = sc[nt];
        mma_f16(c[0], c[1], c[2], c[3], qf[ks][0], qf[ks][1], qf[ks][2],
                qf[ks][3], kf[nt * 2], kf[nt * 2 + 1]);
      }
    }

#pragma unroll
    for (int nt = 0; nt < 8; nt++)
#pragma unroll
      for (int c = 0; c < 4; c++) sc[nt][c] *= SC2;
    if (kbase + 64 > vlen) {
#pragma unroll
      for (int nt = 0; nt < 8; nt++) {
        int k0 = kbase + nt * 8 + cb;
        if (k0 >= vlen) { sc[nt][0] = -1e30f; sc[nt][2] = -1e30f; }
        if (k0 + 1 >= vlen) { sc[nt][1] = -1e30f; sc[nt][3] = -1e30f; }
      }
    }

    // --- online softmax (fp32) ---
    float rm0 = -1e30f, rm1 = -1e30f;
#pragma unroll
    for (int nt = 0; nt < 8; nt++) {
      rm0 = fmaxf(rm0, fmaxf(sc[nt][0], sc[nt][1]));
      rm1 = fmaxf(rm1, fmaxf(sc[nt][2], sc[nt][3]));
    }
    rm0 = fmaxf(rm0, __shfl_xor_sync(0xffffffffu, rm0, 1));
    rm0 = fmaxf(rm0, __shfl_xor_sync(0xffffffffu, rm0, 2));
    rm1 = fmaxf(rm1, __shfl_xor_sync(0xffffffffu, rm1, 1));
    rm1 = fmaxf(rm1, __shfl_xor_sync(0xffffffffu, rm1, 2));
    float mn0 = fmaxf(m0r, rm0), mn1 = fmaxf(m1r, rm1);
    float corr0 = exp2f(m0r - mn0), corr1 = exp2f(m1r - mn1);

    uint32_t pf[8][2];
    float rs0 = 0.f, rs1 = 0.f;
#pragma unroll
    for (int nt = 0; nt < 8; nt++) {
      float p0 = exp2f(sc[nt][0] - mn0);
      float p1 = exp2f(sc[nt][1] - mn0);
      float p2 = exp2f(sc[nt][2] - mn1);
      float p3 = exp2f(sc[nt][3] - mn1);
      rs0 += p0 + p1;
      rs1 += p2 + p3;
      pf[nt][0] = pack_f16(p0, p1);
      pf[nt][1] = pack_f16(p2, p3);
    }
    rs0 += __shfl_xor_sync(0xffffffffu, rs0, 1);
    rs0 += __shfl_xor_sync(0xffffffffu, rs0, 2);
    rs1 += __shfl_xor_sync(0xffffffffu, rs1, 1);
    rs1 += __shfl_xor_sync(0xffffffffu, rs1, 2);
    l0r = l0r * corr0 + rs0;
    l1r = l1r * corr1 + rs1;
    m0r = mn0;
    m1r = mn1;
#pragma unroll
    for (int nt = 0; nt < 8; nt++) {
      oacc[nt][0] *= corr0;
      oacc[nt][1] *= corr0;
      oacc[nt][2] *= corr1;
      oacc[nt][3] *= corr1;
    }

    // --- oacc += P V (fp16 single term) ---
#pragma unroll
    for (int ks = 0; ks < 4; ks++) {
      uint32_t vf[16];
#pragma unroll
      for (int np = 0; np < 4; np++) {
        uint32_t rv = (ks * 16 + v_row) * (RS * 2) + np * 32 + v_col;
        LDMX4T(vf[np * 4 + 0], vf[np * 4 + 1], vf[np * 4 + 2], vf[np * 4 + 3],
               vb16 + rv);
      }
      uint32_t a0 = pf[2 * ks][0], a1 = pf[2 * ks][1];
      uint32_t a2 = pf[2 * ks + 1][0], a3 = pf[2 * ks + 1][1];
#pragma unroll
      for (int nt = 0; nt < 8; nt++) {
        float* c = oacc[nt];
        mma_f16(c[0], c[1], c[2], c[3], a0, a1, a2, a3, vf[nt * 2],
                vf[nt * 2 + 1]);
      }
    }
  }

  // --- epilogue: normalize, split to bf16 hi/lo for the out-projection ---
  float inv0 = 1.f / l0r, inv1 = 1.f / l1r;
  int r0 = q0 + wid * 16 + (l >> 2);
#pragma unroll
  for (int nt = 0; nt < 8; nt++) {
    int col = h * DH + nt * 8 + cb;
    float o0 = oacc[nt][0] * inv0, o1 = oacc[nt][1] * inv0;
    float o2 = oacc[nt][2] * inv1, o3 = oacc[nt][3] * inv1;
    float h0 = __bfloat162float(__float2bfloat16(o0));
    float h1 = __bfloat162float(__float2bfloat16(o1));
    float h2 = __bfloat162float(__float2bfloat16(o2));
    float h3 = __bfloat162float(__float2bfloat16(o3));
    size_t i0 = (size_t)(b * S + r0) * HID + col;
    size_t i1 = (size_t)(b * S + r0 + 8) * HID + col;
    *(uint32_t*)&Oh[i0] = pack_bf16(o0, o1);
    *(uint32_t*)&Ol[i0] = pack_bf16(o0 - h0, o1 - h1);
    *(uint32_t*)&Oh[i1] = pack_bf16(o2, o3);
    *(uint32_t*)&Ol[i1] = pack_bf16(o2 - h2, o3 - h3);
  }
}

// ---------------------------------------------------------------------------
extern "C" void kernel_launch(void* const* d_in, const int* in_sizes, int n_in,
                              void* d_out, int out_size) {
  const float* queries = (const float*)d_in[0];
  const float* keys    = (const float*)d_in[1];
  const float* values  = (const float*)d_in[2];
  const int*   vlens   = (const int*)d_in[3];
  const float* W[4]    = {(const float*)d_in[4], (const float*)d_in[5],
                          (const float*)d_in[6], (const float*)d_in[7]};
  float* out = (float*)d_out;

  __nv_bfloat16 *whb, *wlb, *oh, *ol;
  __half *q16, *k16, *v16;
  cudaGetSymbolAddress((void**)&whb, g_wh);
  cudaGetSymbolAddress((void**)&wlb, g_wl);
  cudaGetSymbolAddress((void**)&q16, g_q16);
  cudaGetSymbolAddress((void**)&k16, g_k16);
  cudaGetSymbolAddress((void**)&v16, g_v16);
  cudaGetSymbolAddress((void**)&oh, g_oh);
  cudaGetSymbolAddress((void**)&ol, g_ol);
  const int WSZ = HID * HID;

  cudaFuncSetAttribute(gemm_tc_hmma<true, true>,
                       cudaFuncAttributeMaxDynamicSharedMemorySize, GEMM_SMEM);
  cudaFuncSetAttribute(gemm_tc_hmma<false, false>,
                       cudaFuncAttributeMaxDynamicSharedMemorySize, GEMM_SMEM);
  cudaFuncSetAttribute(attn_hmma,
                       cudaFuncAttributeMaxDynamicSharedMemorySize, ATTN_SMEM);

  // --- one batched weight split (Wq, Wk, Wv, Wo) ---
  SplitBatch wsb = {};
  for (int i = 0; i < 4; i++) {
    wsb.src[i] = W[i];
    wsb.hi[i] = whb + i * WSZ;
    wsb.lo[i] = wlb + i * WSZ;
  }
  split_batch_kernel<<<dim3(WSZ / 4 / 256, 4), 256>>>(wsb, WSZ / 4);

  // --- Q/K/V projections (bf16x3), fp16 outputs; K/V vlen tiles skipped ---
  GemmBatch gp = {};
  gp.af[0] = queries; gp.af[1] = keys; gp.af[2] = values;
  for (int i = 0; i < 3; i++) {
    gp.wh[i] = whb + i * WSZ;
    gp.wl[i] = wlb + i * WSZ;
  }
  gp.c16[0] = q16; gp.c16[1] = k16; gp.c16[2] = v16;
  gp.vlens = vlens;
  gemm_tc_hmma<true, true>
      <<<dim3(HID / 128, M / 128, 3), 256, GEMM_SMEM>>>(gp);

  // --- attention (fp16 single-term) ---
  attn_hmma<<<dim3(S / 128, NH, B), 256, ATTN_SMEM>>>(q16, k16, v16, vlens,
                                                      oh, ol);

  // --- output projection (bf16x3 on attention output, fp32 out) ---
  GemmBatch go = {};
  go.ah = oh; go.al = ol;
  go.wh[0] = whb + 3 * WSZ;
  go.wl[0] = wlb + 3 * WSZ;
  go.c = out;
  go.vlens = nullptr;
  gemm_tc_hmma<false, false>
      <<<dim3(HID / 128, M / 128, 1), 256, GEMM_SMEM>>>(go);
}

// round 14
// speedup vs baseline: 1.8890x; 1.1342x over previous
#include <cuda_runtime.h>
#include <cuda_bf16.h>
#include <cuda_fp16.h>
#include <cstdint>

// Problem constants
constexpr int B   = 4;
constexpr int S   = 2048;
constexpr int HID = 512;
constexpr int NH  = 8;
constexpr int DH  = 64;
constexpr int M   = B * S;       // 8192

// Scratch (device globals — no runtime allocation allowed)
__device__ __half g_wh16[4][HID * HID], g_wl16[4][HID * HID];
__device__ __half g_q16[M * HID], g_k16[M * HID], g_v16[M * HID];
__device__ __half g_o16[M * HID];

// ---------------------------------------------------------------------------
// mma.sync / ldmatrix / cp.async helpers (plain sm_80+ PTX)
// ---------------------------------------------------------------------------
__device__ __forceinline__ uint32_t smem_u32(const void* p) {
  uint32_t a;
  asm("{ .reg .u64 t; cvta.to.shared.u64 t, %1; cvt.u32.u64 %0, t; }"
      : "=r"(a) : "l"(p));
  return a;
}

#define LDMX4(r0, r1, r2, r3, addr)                                       \
  asm volatile(                                                           \
      "ldmatrix.sync.aligned.m8n8.x4.shared.b16 {%0,%1,%2,%3}, [%4];"     \
      : "=r"(r0), "=r"(r1), "=r"(r2), "=r"(r3) : "r"(addr))

#define LDMX4T(r0, r1, r2, r3, addr)                                      \
  asm volatile(                                                           \
      "ldmatrix.sync.aligned.m8n8.x4.trans.shared.b16 {%0,%1,%2,%3}, [%4];" \
      : "=r"(r0), "=r"(r1), "=r"(r2), "=r"(r3) : "r"(addr))

#define CP_ASYNC16(dst, src)                                              \
  asm volatile("cp.async.cg.shared.global [%0], [%1], 16;" ::             \
                   "r"(dst), "l"(src))
#define CP_COMMIT() asm volatile("cp.async.commit_group;" ::: "memory")
#define CP_WAIT0() asm volatile("cp.async.wait_group 0;" ::: "memory")
#define CP_WAIT1() asm volatile("cp.async.wait_group 1;" ::: "memory")

__device__ __forceinline__ void mma_f16(float& c0, float& c1, float& c2,
                                        float& c3, uint32_t a0, uint32_t a1,
                                        uint32_t a2, uint32_t a3,
                                        uint32_t b0, uint32_t b1) {
  asm volatile(
      "mma.sync.aligned.m16n8k16.row.col.f32.f16.f16.f32 "
      "{%0,%1,%2,%3}, {%4,%5,%6,%7}, {%8,%9}, {%0,%1,%2,%3};"
      : "+f"(c0), "+f"(c1), "+f"(c2), "+f"(c3)
      : "r"(a0), "r"(a1), "r"(a2), "r"(a3), "r"(b0), "r"(b1));
}

__device__ __forceinline__ uint32_t pack_f16(float a, float b) {
  __half2 t = __floats2half2_rn(a, b);
  return *(uint32_t*)&t;
}

// ---------------------------------------------------------------------------
// Weight split: fp32 -> fp16 hi + fp16 lo (2-term; residual ~2^-22, exact
// enough that projection error is dominated by the A-side fp16 quantization).
// ---------------------------------------------------------------------------
struct SplitBatch {
  const float* src[4];
  __half* hi[4];
  __half* lo[4];
};

__global__ __launch_bounds__(256) void split_batch_kernel(SplitBatch sb,
                                                          int n4) {
  int i = blockIdx.x * blockDim.x + threadIdx.x;
  if (i >= n4) return;
  int z = blockIdx.y;
  float4 v = ((const float4*)sb.src[z])[i];
  float hx = __half2float(__float2half_rn(v.x));
  float hy = __half2float(__float2half_rn(v.y));
  float hz = __half2float(__float2half_rn(v.z));
  float hw = __half2float(__float2half_rn(v.w));
  uint2 ho, lw;
  ho.x = pack_f16(v.x, v.y);
  ho.y = pack_f16(v.z, v.w);
  lw.x = pack_f16(v.x - hx, v.y - hy);
  lw.y = pack_f16(v.z - hz, v.w - hw);
  ((uint2*)sb.hi[z])[i] = ho;
  ((uint2*)sb.lo[z])[i] = lw;
}

// ---------------------------------------------------------------------------
// HMMA fp16x2 GEMM-NT: C = A16 @ (Wh + Wl)^T — 2 MMA terms per k16.
// A: single fp16 tile (AFP32: fused fp32->fp16 conversion; else cp.async).
// W: fp16 hi/lo, cp.async double-buffered (2 stages).
// QKV (F16OUT): fp16 outputs; K/V m-tiles beyond valid_len skipped.
// Out-proj (!F16OUT): fp32 output to d_out.
// ---------------------------------------------------------------------------
constexpr int RS = 72;                    // smem row stride in halfs (144 B)
constexpr int TILE_BYTES = 128 * RS * 2;  // 18432 per tile
constexpr int SA16 = 0;                   // A: 1 tile
constexpr int SW_BASE = TILE_BYTES;       // 18432
constexpr int W_STG = 2 * TILE_BYTES;     // Wh+Wl per stage
constexpr int GEMM_SMEM = SW_BASE + 2 * W_STG;  // 92160 (x2 CTAs fits)

struct GemmBatch {
  const float* af[3];                 // AFP32 inputs
  const __half* a16;                  // !AFP32 input (out-proj A = O fp16)
  const __half* wh[3];
  const __half* wl[3];
  __half* c16[3];                     // F16OUT outputs
  float* c;                           // !F16OUT output
  const int* vlens;                   // valid_lens (skip for z=1,2); null ok
};

template <bool AFP32, bool F16OUT>
__global__ __launch_bounds__(256, 2) void gemm_tc_hmma(GemmBatch p) {
  extern __shared__ __align__(128) char smem[];
  const uint32_t sb = smem_u32(smem);
  const int t = threadIdx.x;
  const int wid = t >> 5, l = t & 31;
  const int wm = wid >> 2;
  const int wn = wid & 3;
  const int m0 = blockIdx.y * 128;
  const int n0 = blockIdx.x * 128;
  const int z = blockIdx.z;

  if (AFP32 && z != 0) {
    int vl = p.vlens[m0 >> 11];       // batch = m0 / S (S = 2048)
    if ((m0 & (S - 1)) >= vl) return;
  }

  const __half* Wh = p.wh[z];
  const __half* Wl = p.wl[z];

  auto issue_w = [&](int stage, int kc) {
    const int koff = kc * 64;
#pragma unroll
    for (int i = 0; i < 8; i++) {
      int idx = t + i * 256;
      int comp = idx >> 10;             // 0: Wh, 1: Wl
      int r = (idx >> 3) & 127;
      int c = idx & 7;
      const __half* src =
          (comp ? Wl : Wh) + (size_t)(n0 + r) * HID + koff + c * 8;
      uint32_t dst = sb + SW_BASE + stage * W_STG + comp * TILE_BYTES +
                     r * (RS * 2) + c * 16;
      CP_ASYNC16(dst, src);
    }
  };

  issue_w(0, 0);
  CP_COMMIT();

  float acc[4][4][4] = {};

  const int a_row = (l & 15);
  const int a_koff = ((l >> 4) & 1) * 16;
  const int b_row = (l & 7) + ((l >> 4) & 1) * 8;
  const int b_koff = ((l >> 3) & 1) * 16;

  for (int kc = 0; kc < 8; kc++) {
    const int koff = kc * 64;
    if constexpr (AFP32) {
      const float* Af = p.af[z];
#pragma unroll
      for (int i = 0; i < 8; i++) {     // 2048 float4 -> fp16 x4
        int v = t + i * 256;
        int row = v >> 4, c = v & 15;
        float4 fv = *(const float4*)(Af + (size_t)(m0 + row) * HID + koff +
                                     c * 4);
        uint2 ho;
        ho.x = pack_f16(fv.x, fv.y);
        ho.y = pack_f16(fv.z, fv.w);
        *(uint2*)(smem + SA16 + row * (RS * 2) + c * 8) = ho;
      }
    } else {
#pragma unroll
      for (int i = 0; i < 4; i++) {     // 1024 x 16B cp.async
        int idx = t + i * 256;
        int r = idx >> 3;
        int c = idx & 7;
        const __half* src = p.a16 + (size_t)(m0 + r) * HID + koff + c * 8;
        uint32_t dst = sb + SA16 + r * (RS * 2) + c * 16;
        CP_ASYNC16(dst, src);
      }
      CP_COMMIT();
    }
    if (kc + 1 < 8) {
      issue_w((kc + 1) & 1, kc + 1);
      CP_COMMIT();
      CP_WAIT1();
    } else {
      CP_WAIT0();
    }
    __syncthreads();
    const uint32_t st_w = sb + SW_BASE + (kc & 1) * W_STG;

#pragma unroll
    for (int ks = 0; ks < 4; ks++) {
      const int kb = ks * 32;
      uint32_t af[4][4], bh[8], bl[8];
#pragma unroll
      for (int mt = 0; mt < 4; mt++) {
        uint32_t ra = (wm * 64 + mt * 16 + a_row) * (RS * 2) + kb + a_koff;
        LDMX4(af[mt][0], af[mt][1], af[mt][2], af[mt][3], sb + SA16 + ra);
      }
#pragma unroll
      for (int np = 0; np < 2; np++) {
        uint32_t rb = (wn * 32 + np * 16 + b_row) * (RS * 2) + kb + b_koff;
        LDMX4(bh[np * 4 + 0], bh[np * 4 + 1], bh[np * 4 + 2], bh[np * 4 + 3],
              st_w + rb);
        LDMX4(bl[np * 4 + 0], bl[np * 4 + 1], bl[np * 4 + 2], bl[np * 4 + 3],
              st_w + TILE_BYTES + rb);
      }
#pragma unroll
      for (int mt = 0; mt < 4; mt++)
#pragma unroll
        for (int nt = 0; nt < 4; nt++) {
          float* c = acc[mt][nt];
          mma_f16(c[0], c[1], c[2], c[3], af[mt][0], af[mt][1], af[mt][2],
                  af[mt][3], bh[nt * 2], bh[nt * 2 + 1]);
          mma_f16(c[0], c[1], c[2], c[3], af[mt][0], af[mt][1], af[mt][2],
                  af[mt][3], bl[nt * 2], bl[nt * 2 + 1]);
        }
    }
    __syncthreads();
  }

  const int er = l >> 2, ec = (l & 3) * 2;
#pragma unroll
  for (int mt = 0; mt < 4; mt++) {
    int row = m0 + wm * 64 + mt * 16 + er;
#pragma unroll
    for (int nt = 0; nt < 4; nt++) {
      int col = n0 + wn * 32 + nt * 8 + ec;
      float* a = acc[mt][nt];
      if constexpr (F16OUT) {
        size_t i0 = (size_t)row * HID + col;
        size_t i1 = (size_t)(row + 8) * HID + col;
        *(uint32_t*)&p.c16[z][i0] = pack_f16(a[0], a[1]);
        *(uint32_t*)&p.c16[z][i1] = pack_f16(a[2], a[3]);
      } else {
        *(float2*)&p.c[(size_t)row * HID + col] = make_float2(a[0], a[1]);
        *(float2*)&p.c[(size_t)(row + 8) * HID + col] =
            make_float2(a[2], a[3]);
      }
    }
  }
}

// ---------------------------------------------------------------------------
// fp16 flash attention (single-term QK and PV, fp32 softmax) — round-13
// structure; epilogue now emits single fp16 O for the fp16x2 out-projection.
// ---------------------------------------------------------------------------
constexpr float SC2 = 0.125f * 1.4426950408889634f;  // (1/8)*log2(e)

constexpr int AQ16 = 0;                        // Q fp16: 128 x 144B
constexpr int ASTG0 = 128 * RS * 2;            // 18432
constexpr int AKV_COMP = 64 * RS * 2;          // 9216 (K or V per stage)
constexpr int ASTG_SZ = 2 * AKV_COMP;          // 18432
constexpr int ATTN_SMEM = ASTG0 + 2 * ASTG_SZ; // 55296

__global__ __launch_bounds__(256, 2) void attn_hmma(
    const __half* __restrict__ Q16, const __half* __restrict__ K16,
    const __half* __restrict__ V16, const int* __restrict__ valid_lens,
    __half* __restrict__ O16) {
  extern __shared__ __align__(128) char smem[];
  const uint32_t sb = smem_u32(smem);
  const int qt = blockIdx.x, h = blockIdx.y, b = blockIdx.z;
  const int t = threadIdx.x;
  const int wid = t >> 5, l = t & 31;
  const int q0 = qt * 128;
  const int vlen = valid_lens[b];
  const int ntiles = (vlen + 63) >> 6;

  auto issue_tile = [&](int stage, int kbase) {
#pragma unroll
    for (int i = 0; i < 4; i++) {       // 1024 x 16B cp.async
      int idx = t + i * 256;
      int comp = idx >> 9;              // 0: K, 1: V
      int r = (idx >> 3) & 63;
      int c = idx & 7;
      const __half* src =
          (comp ? V16 : K16) + (size_t)(b * S + kbase + r) * HID + h * DH +
          c * 8;
      uint32_t dst = sb + ASTG0 + stage * ASTG_SZ + comp * AKV_COMP +
                     r * (RS * 2) + c * 16;
      CP_ASYNC16(dst, src);
    }
  };

  issue_tile(0, 0);
  CP_COMMIT();
#pragma unroll
  for (int i = 0; i < 4; i++) {         // Q tile: 1024 x 16B
    int v = t + i * 256;
    int row = v >> 3, c = v & 7;
    size_t g = (size_t)(b * S + q0 + row) * HID + h * DH + c * 8;
    *(uint4*)(smem + AQ16 + row * (RS * 2) + c * 16) =
        *(const uint4*)(Q16 + g);
  }
  __syncthreads();

  const int a_row = (l & 15);
  const int a_koff = ((l >> 4) & 1) * 16;
  const int b_row = (l & 7) + ((l >> 4) & 1) * 8;
  const int b_koff = ((l >> 3) & 1) * 16;
  const int v_row = (l & 7) + ((l >> 3) & 1) * 8;
  const int v_col = ((l >> 4) & 1) * 16;
  const int cb = (l & 3) * 2;

  uint32_t qf[4][4];
#pragma unroll
  for (int ks = 0; ks < 4; ks++) {
    uint32_t ra = (wid * 16 + a_row) * (RS * 2) + ks * 32 + a_koff;
    LDMX4(qf[ks][0], qf[ks][1], qf[ks][2], qf[ks][3], sb + AQ16 + ra);
  }

  float oacc[8][4] = {};
  float m0r = -1e30f, m1r = -1e30f, l0r = 0.f, l1r = 0.f;

  for (int kt = 0; kt < ntiles; kt++) {
    const int kbase = kt * 64;
    const uint32_t kb16 = sb + ASTG0 + (kt & 1) * ASTG_SZ;
    const uint32_t vb16 = kb16 + AKV_COMP;

    CP_WAIT0();
    __syncthreads();
    if (kt + 1 < ntiles) {
      issue_tile((kt + 1) & 1, kbase + 64);
      CP_COMMIT();
    }

    float sc[8][4];
#pragma unroll
    for (int nt = 0; nt < 8; nt++)
#pragma unroll
      for (int c = 0; c < 4; c++) sc[nt][c] = 0.f;
#pragma unroll
    for (int ks = 0; ks < 4; ks++) {
      uint32_t kf[16];
#pragma unroll
      for (int np = 0; np < 4; np++) {
        uint32_t rb = (np * 16 + b_row) * (RS * 2) + ks * 32 + b_koff;
        LDMX4(kf[np * 4 + 0], kf[np * 4 + 1], kf[np * 4 + 2], kf[np * 4 + 3],
              kb16 + rb);
      }
#pragma unroll
      for (int nt = 0; nt < 8; nt++) {
        float* c = sc[nt];
        mma_f16(c[0], c[1], c[2], c[3], qf[ks][0], qf[ks][1], qf[ks][2],
                qf[ks][3], kf[nt * 2], kf[nt * 2 + 1]);
      }
    }

#pragma unroll
    for (int nt = 0; nt < 8; nt++)
#pragma unroll
      for (int c = 0; c < 4; c++) sc[nt][c] *= SC2;
    if (kbase + 64 > vlen) {
#pragma unroll
      for (int nt = 0; nt < 8; nt++) {
        int k0 = kbase + nt * 8 + cb;
        if (k0 >= vlen) { sc[nt][0] = -1e30f; sc[nt][2] = -1e30f; }
        if (k0 + 1 >= vlen) { sc[nt][1] = -1e30f; sc[nt][3] = -1e30f; }
      }
    }

    float rm0 = -1e30f, rm1 = -1e30f;
#pragma unroll
    for (int nt = 0; nt < 8; nt++) {
      rm0 = fmaxf(rm0, fmaxf(sc[nt][0], sc[nt][1]));
      rm1 = fmaxf(rm1, fmaxf(sc[nt][2], sc[nt][3]));
    }
    rm0 = fmaxf(rm0, __shfl_xor_sync(0xffffffffu, rm0, 1));
    rm0 = fmaxf(rm0, __shfl_xor_sync(0xffffffffu, rm0, 2));
    rm1 = fmaxf(rm1, __shfl_xor_sync(0xffffffffu, rm1, 1));
    rm1 = fmaxf(rm1, __shfl_xor_sync(0xffffffffu, rm1, 2));
    float mn0 = fmaxf(m0r, rm0), mn1 = fmaxf(m1r, rm1);
    float corr0 = exp2f(m0r - mn0), corr1 = exp2f(m1r - mn1);

    uint32_t pf[8][2];
    float rs0 = 0.f, rs1 = 0.f;
#pragma unroll
    for (int nt = 0; nt < 8; nt++) {
      float p0 = exp2f(sc[nt][0] - mn0);
      float p1 = exp2f(sc[nt][1] - mn0);
      float p2 = exp2f(sc[nt][2] - mn1);
      float p3 = exp2f(sc[nt][3] - mn1);
      rs0 += p0 + p1;
      rs1 += p2 + p3;
      pf[nt][0] = pack_f16(p0, p1);
      pf[nt][1] = pack_f16(p2, p3);
    }
    rs0 += __shfl_xor_sync(0xffffffffu, rs0, 1);
    rs0 += __shfl_xor_sync(0xffffffffu, rs0, 2);
    rs1 += __shfl_xor_sync(0xffffffffu, rs1, 1);
    rs1 += __shfl_xor_sync(0xffffffffu, rs1, 2);
    l0r = l0r * corr0 + rs0;
    l1r = l1r * corr1 + rs1;
    m0r = mn0;
    m1r = mn1;
#pragma unroll
    for (int nt = 0; nt < 8; nt++) {
      oacc[nt][0] *= corr0;
      oacc[nt][1] *= corr0;
      oacc[nt][2] *= corr1;
      oacc[nt][3] *= corr1;
    }

#pragma unroll
    for (int ks = 0; ks < 4; ks++) {
      uint32_t vf[16];
#pragma unroll
      for (int np = 0; np < 4; np++) {
        uint32_t rv = (ks * 16 + v_row) * (RS * 2) + np * 32 + v_col;
        LDMX4T(vf[np * 4 + 0], vf[np * 4 + 1], vf[np * 4 + 2], vf[np * 4 + 3],
               vb16 + rv);
      }
      uint32_t a0 = pf[2 * ks][0], a1 = pf[2 * ks][1];
      uint32_t a2 = pf[2 * ks + 1][0], a3 = pf[2 * ks + 1][1];
#pragma unroll
      for (int nt = 0; nt < 8; nt++) {
        float* c = oacc[nt];
        mma_f16(c[0], c[1], c[2], c[3], a0, a1, a2, a3, vf[nt * 2],
                vf[nt * 2 + 1]);
      }
    }
  }

  float inv0 = 1.f / l0r, inv1 = 1.f / l1r;
  int r0 = q0 + wid * 16 + (l >> 2);
#pragma unroll
  for (int nt = 0; nt < 8; nt++) {
    int col = h * DH + nt * 8 + cb;
    size_t i0 = (size_t)(b * S + r0) * HID + col;
    size_t i1 = (size_t)(b * S + r0 + 8) * HID + col;
    *(uint32_t*)&O16[i0] = pack_f16(oacc[nt][0] * inv0, oacc[nt][1] * inv0);
    *(uint32_t*)&O16[i1] = pack_f16(oacc[nt][2] * inv1, oacc[nt][3] * inv1);
  }
}

// ---------------------------------------------------------------------------
extern "C" void kernel_launch(void* const* d_in, const int* in_sizes, int n_in,
                              void* d_out, int out_size) {
  const float* queries = (const float*)d_in[0];
  const float* keys    = (const float*)d_in[1];
  const float* values  = (const float*)d_in[2];
  const int*   vlens   = (const int*)d_in[3];
  const float* W[4]    = {(const float*)d_in[4], (const float*)d_in[5],
                          (const float*)d_in[6], (const float*)d_in[7]};
  float* out = (float*)d_out;

  __half *whb, *wlb, *q16, *k16, *v16, *o16;
  cudaGetSymbolAddress((void**)&whb, g_wh16);
  cudaGetSymbolAddress((void**)&wlb, g_wl16);
  cudaGetSymbolAddress((void**)&q16, g_q16);
  cudaGetSymbolAddress((void**)&k16, g_k16);
  cudaGetSymbolAddress((void**)&v16, g_v16);
  cudaGetSymbolAddress((void**)&o16, g_o16);
  const int WSZ = HID * HID;

  cudaFuncSetAttribute(gemm_tc_hmma<true, true>,
                       cudaFuncAttributeMaxDynamicSharedMemorySize, GEMM_SMEM);
  cudaFuncSetAttribute(gemm_tc_hmma<false, false>,
                       cudaFuncAttributeMaxDynamicSharedMemorySize, GEMM_SMEM);
  cudaFuncSetAttribute(attn_hmma,
                       cudaFuncAttributeMaxDynamicSharedMemorySize, ATTN_SMEM);

  // --- one batched weight split (Wq, Wk, Wv, Wo) -> fp16 hi/lo ---
  SplitBatch wsb = {};
  for (int i = 0; i < 4; i++) {
    wsb.src[i] = W[i];
    wsb.hi[i] = whb + i * WSZ;
    wsb.lo[i] = wlb + i * WSZ;
  }
  split_batch_kernel<<<dim3(WSZ / 4 / 256, 4), 256>>>(wsb, WSZ / 4);

  // --- Q/K/V projections (fp16x2), fp16 outputs; K/V vlen tiles skipped ---
  GemmBatch gp = {};
  gp.af[0] = queries; gp.af[1] = keys; gp.af[2] = values;
  for (int i = 0; i < 3; i++) {
    gp.wh[i] = whb + i * WSZ;
    gp.wl[i] = wlb + i * WSZ;
  }
  gp.c16[0] = q16; gp.c16[1] = k16; gp.c16[2] = v16;
  gp.vlens = vlens;
  gemm_tc_hmma<true, true>
      <<<dim3(HID / 128, M / 128, 3), 256, GEMM_SMEM>>>(gp);

  // --- attention (fp16 single-term) ---
  attn_hmma<<<dim3(S / 128, NH, B), 256, ATTN_SMEM>>>(q16, k16, v16, vlens,
                                                      o16);

  // --- output projection (fp16x2 on fp16 O, fp32 out) ---
  GemmBatch go = {};
  go.a16 = o16;
  go.wh[0] = whb + 3 * WSZ;
  go.wl[0] = wlb + 3 * WSZ;
  go.c = out;
  go.vlens = nullptr;
  gemm_tc_hmma<false, false>
      <<<dim3(HID / 128, M / 128, 1), 256, GEMM_SMEM>>>(go);
}

// round 15
// speedup vs baseline: 1.9260x; 1.0196x over previous
#include <cuda_runtime.h>
#include <cuda_bf16.h>
#include <cuda_fp16.h>
#include <cstdint>

// Problem constants
constexpr int B   = 4;
constexpr int S   = 2048;
constexpr int HID = 512;
constexpr int NH  = 8;
constexpr int DH  = 64;
constexpr int M   = B * S;       // 8192

// Scratch (device globals — no runtime allocation allowed)
__device__ __half g_wh16[4][HID * HID], g_wl16[4][HID * HID];
__device__ __half g_q16[M * HID], g_k16[M * HID], g_v16[M * HID];
__device__ __half g_o16[M * HID];

// ---------------------------------------------------------------------------
// mma.sync / ldmatrix / cp.async helpers (plain sm_80+ PTX)
// ---------------------------------------------------------------------------
__device__ __forceinline__ uint32_t smem_u32(const void* p) {
  uint32_t a;
  asm("{ .reg .u64 t; cvta.to.shared.u64 t, %1; cvt.u32.u64 %0, t; }"
      : "=r"(a) : "l"(p));
  return a;
}

#define LDMX4(r0, r1, r2, r3, addr)                                       \
  asm volatile(                                                           \
      "ldmatrix.sync.aligned.m8n8.x4.shared.b16 {%0,%1,%2,%3}, [%4];"     \
      : "=r"(r0), "=r"(r1), "=r"(r2), "=r"(r3) : "r"(addr))

#define LDMX4T(r0, r1, r2, r3, addr)                                      \
  asm volatile(                                                           \
      "ldmatrix.sync.aligned.m8n8.x4.trans.shared.b16 {%0,%1,%2,%3}, [%4];" \
      : "=r"(r0), "=r"(r1), "=r"(r2), "=r"(r3) : "r"(addr))

#define CP_ASYNC16(dst, src)                                              \
  asm volatile("cp.async.cg.shared.global [%0], [%1], 16;" ::             \
                   "r"(dst), "l"(src))
#define CP_COMMIT() asm volatile("cp.async.commit_group;" ::: "memory")
#define CP_WAIT0() asm volatile("cp.async.wait_group 0;" ::: "memory")
#define CP_WAIT1() asm volatile("cp.async.wait_group 1;" ::: "memory")

__device__ __forceinline__ void mma_f16(float& c0, float& c1, float& c2,
                                        float& c3, uint32_t a0, uint32_t a1,
                                        uint32_t a2, uint32_t a3,
                                        uint32_t b0, uint32_t b1) {
  asm volatile(
      "mma.sync.aligned.m16n8k16.row.col.f32.f16.f16.f32 "
      "{%0,%1,%2,%3}, {%4,%5,%6,%7}, {%8,%9}, {%0,%1,%2,%3};"
      : "+f"(c0), "+f"(c1), "+f"(c2), "+f"(c3)
      : "r"(a0), "r"(a1), "r"(a2), "r"(a3), "r"(b0), "r"(b1));
}

__device__ __forceinline__ uint32_t pack_f16(float a, float b) {
  __half2 t = __floats2half2_rn(a, b);
  return *(uint32_t*)&t;
}

// ---------------------------------------------------------------------------
// Weight split: fp32 -> fp16 hi + fp16 lo (2-term; residual ~2^-22).
// ---------------------------------------------------------------------------
struct SplitBatch {
  const float* src[4];
  __half* hi[4];
  __half* lo[4];
};

__global__ __launch_bounds__(256) void split_batch_kernel(SplitBatch sb,
                                                          int n4) {
  int i = blockIdx.x * blockDim.x + threadIdx.x;
  if (i >= n4) return;
  int z = blockIdx.y;
  float4 v = ((const float4*)sb.src[z])[i];
  float hx = __half2float(__float2half_rn(v.x));
  float hy = __half2float(__float2half_rn(v.y));
  float hz = __half2float(__float2half_rn(v.z));
  float hw = __half2float(__float2half_rn(v.w));
  uint2 ho, lw;
  ho.x = pack_f16(v.x, v.y);
  ho.y = pack_f16(v.z, v.w);
  lw.x = pack_f16(v.x - hx, v.y - hy);
  lw.y = pack_f16(v.z - hz, v.w - hw);
  ((uint2*)sb.hi[z])[i] = ho;
  ((uint2*)sb.lo[z])[i] = lw;
}

// ---------------------------------------------------------------------------
// HMMA fp16x2 GEMM-NT: C = A16 @ (Wh + Wl)^T — 2 MMA terms per k16.
// A: single fp16 tile (AFP32: fused fp32->fp16 conversion; else cp.async).
// W: fp16 hi/lo, cp.async double-buffered (2 stages).
// QKV (F16OUT): fp16 outputs; K/V m-tiles beyond valid_len skipped.
// Out-proj (!F16OUT): fp32 output to d_out.
// ---------------------------------------------------------------------------
constexpr int RS = 72;                    // smem row stride in halfs (144 B)
constexpr int TILE_BYTES = 128 * RS * 2;  // 18432 per tile
constexpr int SA16 = 0;                   // A: 1 tile
constexpr int SW_BASE = TILE_BYTES;       // 18432
constexpr int W_STG = 2 * TILE_BYTES;     // Wh+Wl per stage
constexpr int GEMM_SMEM = SW_BASE + 2 * W_STG;  // 92160 (x2 CTAs fits)

struct GemmBatch {
  const float* af[3];                 // AFP32 inputs
  const __half* a16;                  // !AFP32 input (out-proj A = O fp16)
  const __half* wh[3];
  const __half* wl[3];
  __half* c16[3];                     // F16OUT outputs
  float* c;                           // !F16OUT output
  const int* vlens;                   // valid_lens (skip for z=1,2); null ok
};

template <bool AFP32, bool F16OUT>
__global__ __launch_bounds__(256, 2) void gemm_tc_hmma(GemmBatch p) {
  extern __shared__ __align__(128) char smem[];
  const uint32_t sb = smem_u32(smem);
  const int t = threadIdx.x;
  const int wid = t >> 5, l = t & 31;
  const int wm = wid >> 2;
  const int wn = wid & 3;
  const int m0 = blockIdx.y * 128;
  const int n0 = blockIdx.x * 128;
  const int z = blockIdx.z;

  if (AFP32 && z != 0) {
    int vl = p.vlens[m0 >> 11];       // batch = m0 / S (S = 2048)
    if ((m0 & (S - 1)) >= vl) return;
  }

  const __half* Wh = p.wh[z];
  const __half* Wl = p.wl[z];

  auto issue_w = [&](int stage, int kc) {
    const int koff = kc * 64;
#pragma unroll
    for (int i = 0; i < 8; i++) {
      int idx = t + i * 256;
      int comp = idx >> 10;             // 0: Wh, 1: Wl
      int r = (idx >> 3) & 127;
      int c = idx & 7;
      const __half* src =
          (comp ? Wl : Wh) + (size_t)(n0 + r) * HID + koff + c * 8;
      uint32_t dst = sb + SW_BASE + stage * W_STG + comp * TILE_BYTES +
                     r * (RS * 2) + c * 16;
      CP_ASYNC16(dst, src);
    }
  };

  issue_w(0, 0);
  CP_COMMIT();

  float acc[4][4][4] = {};

  const int a_row = (l & 15);
  const int a_koff = ((l >> 4) & 1) * 16;
  const int b_row = (l & 7) + ((l >> 4) & 1) * 8;
  const int b_koff = ((l >> 3) & 1) * 16;

  for (int kc = 0; kc < 8; kc++) {
    const int koff = kc * 64;
    if constexpr (AFP32) {
      const float* Af = p.af[z];
#pragma unroll
      for (int i = 0; i < 8; i++) {     // 2048 float4 -> fp16 x4
        int v = t + i * 256;
        int row = v >> 4, c = v & 15;
        float4 fv = *(const float4*)(Af + (size_t)(m0 + row) * HID + koff +
                                     c * 4);
        uint2 ho;
        ho.x = pack_f16(fv.x, fv.y);
        ho.y = pack_f16(fv.z, fv.w);
        *(uint2*)(smem + SA16 + row * (RS * 2) + c * 8) = ho;
      }
    } else {
#pragma unroll
      for (int i = 0; i < 4; i++) {     // 1024 x 16B cp.async
        int idx = t + i * 256;
        int r = idx >> 3;
        int c = idx & 7;
        const __half* src = p.a16 + (size_t)(m0 + r) * HID + koff + c * 8;
        uint32_t dst = sb + SA16 + r * (RS * 2) + c * 16;
        CP_ASYNC16(dst, src);
      }
      CP_COMMIT();
    }
    if (kc + 1 < 8) {
      issue_w((kc + 1) & 1, kc + 1);
      CP_COMMIT();
      CP_WAIT1();
    } else {
      CP_WAIT0();
    }
    __syncthreads();
    const uint32_t st_w = sb + SW_BASE + (kc & 1) * W_STG;

#pragma unroll
    for (int ks = 0; ks < 4; ks++) {
      const int kb = ks * 32;
      uint32_t af[4][4], bh[8], bl[8];
#pragma unroll
      for (int mt = 0; mt < 4; mt++) {
        uint32_t ra = (wm * 64 + mt * 16 + a_row) * (RS * 2) + kb + a_koff;
        LDMX4(af[mt][0], af[mt][1], af[mt][2], af[mt][3], sb + SA16 + ra);
      }
#pragma unroll
      for (int np = 0; np < 2; np++) {
        uint32_t rb = (wn * 32 + np * 16 + b_row) * (RS * 2) + kb + b_koff;
        LDMX4(bh[np * 4 + 0], bh[np * 4 + 1], bh[np * 4 + 2], bh[np * 4 + 3],
              st_w + rb);
        LDMX4(bl[np * 4 + 0], bl[np * 4 + 1], bl[np * 4 + 2], bl[np * 4 + 3],
              st_w + TILE_BYTES + rb);
      }
#pragma unroll
      for (int mt = 0; mt < 4; mt++)
#pragma unroll
        for (int nt = 0; nt < 4; nt++) {
          float* c = acc[mt][nt];
          mma_f16(c[0], c[1], c[2], c[3], af[mt][0], af[mt][1], af[mt][2],
                  af[mt][3], bh[nt * 2], bh[nt * 2 + 1]);
          mma_f16(c[0], c[1], c[2], c[3], af[mt][0], af[mt][1], af[mt][2],
                  af[mt][3], bl[nt * 2], bl[nt * 2 + 1]);
        }
    }
    __syncthreads();
  }

  const int er = l >> 2, ec = (l & 3) * 2;
#pragma unroll
  for (int mt = 0; mt < 4; mt++) {
    int row = m0 + wm * 64 + mt * 16 + er;
#pragma unroll
    for (int nt = 0; nt < 4; nt++) {
      int col = n0 + wn * 32 + nt * 8 + ec;
      float* a = acc[mt][nt];
      if constexpr (F16OUT) {
        size_t i0 = (size_t)row * HID + col;
        size_t i1 = (size_t)(row + 8) * HID + col;
        *(uint32_t*)&p.c16[z][i0] = pack_f16(a[0], a[1]);
        *(uint32_t*)&p.c16[z][i1] = pack_f16(a[2], a[3]);
      } else {
        *(float2*)&p.c[(size_t)row * HID + col] = make_float2(a[0], a[1]);
        *(float2*)&p.c[(size_t)(row + 8) * HID + col] =
            make_float2(a[2], a[3]);
      }
    }
  }
}

// ---------------------------------------------------------------------------
// fp16 flash attention (single-term QK and PV, fp32 softmax).
// LPT batch scheduling: blockIdx.z (slowest grid dim) maps to the z-th
// LARGEST-vlen batch, so the heaviest work starts in wave 1 and short CTAs
// pack the tail (makespan -> max(longest plane, total/slots)). Whole-batch
// z-plane grouping is preserved (round-11 showed interleaving batches within
// a wave hurts L2 K/V sharing).
// ---------------------------------------------------------------------------
constexpr float SC2 = 0.125f * 1.4426950408889634f;  // (1/8)*log2(e)

constexpr int AQ16 = 0;                        // Q fp16: 128 x 144B
constexpr int ASTG0 = 128 * RS * 2;            // 18432
constexpr int AKV_COMP = 64 * RS * 2;          // 9216 (K or V per stage)
constexpr int ASTG_SZ = 2 * AKV_COMP;          // 18432
constexpr int ATTN_SMEM = ASTG0 + 2 * ASTG_SZ; // 55296

__global__ __launch_bounds__(256, 2) void attn_hmma(
    const __half* __restrict__ Q16, const __half* __restrict__ K16,
    const __half* __restrict__ V16, const int* __restrict__ valid_lens,
    __half* __restrict__ O16) {
  extern __shared__ __align__(128) char smem[];
  const uint32_t sb = smem_u32(smem);
  const int qt = blockIdx.x, h = blockIdx.y;
  const int t = threadIdx.x;
  const int wid = t >> 5, l = t & 31;
  const int q0 = qt * 128;

  // LPT: map z to the z-th largest-vlen batch (ties broken by index).
  int b = 0;
  {
    const int z = blockIdx.z;
    int v0 = valid_lens[0], v1 = valid_lens[1];
    int v2 = valid_lens[2], v3 = valid_lens[3];
    int v[4] = {v0, v1, v2, v3};
#pragma unroll
    for (int i = 0; i < 4; i++) {
      int r = 0;
#pragma unroll
      for (int j = 0; j < 4; j++)
        r += (v[j] > v[i]) || (v[j] == v[i] && j < i);
      if (r == z) b = i;
    }
  }
  const int vlen = valid_lens[b];
  const int ntiles = (vlen + 63) >> 6;

  auto issue_tile = [&](int stage, int kbase) {
#pragma unroll
    for (int i = 0; i < 4; i++) {       // 1024 x 16B cp.async
      int idx = t + i * 256;
      int comp = idx >> 9;              // 0: K, 1: V
      int r = (idx >> 3) & 63;
      int c = idx & 7;
      const __half* src =
          (comp ? V16 : K16) + (size_t)(b * S + kbase + r) * HID + h * DH +
          c * 8;
      uint32_t dst = sb + ASTG0 + stage * ASTG_SZ + comp * AKV_COMP +
                     r * (RS * 2) + c * 16;
      CP_ASYNC16(dst, src);
    }
  };

  issue_tile(0, 0);
  CP_COMMIT();
#pragma unroll
  for (int i = 0; i < 4; i++) {         // Q tile: 1024 x 16B
    int v = t + i * 256;
    int row = v >> 3, c = v & 7;
    size_t g = (size_t)(b * S + q0 + row) * HID + h * DH + c * 8;
    *(uint4*)(smem + AQ16 + row * (RS * 2) + c * 16) =
        *(const uint4*)(Q16 + g);
  }
  __syncthreads();

  const int a_row = (l & 15);
  const int a_koff = ((l >> 4) & 1) * 16;
  const int b_row = (l & 7) + ((l >> 4) & 1) * 8;
  const int b_koff = ((l >> 3) & 1) * 16;
  const int v_row = (l & 7) + ((l >> 3) & 1) * 8;
  const int v_col = ((l >> 4) & 1) * 16;
  const int cb = (l & 3) * 2;

  uint32_t qf[4][4];
#pragma unroll
  for (int ks = 0; ks < 4; ks++) {
    uint32_t ra = (wid * 16 + a_row) * (RS * 2) + ks * 32 + a_koff;
    LDMX4(qf[ks][0], qf[ks][1], qf[ks][2], qf[ks][3], sb + AQ16 + ra);
  }

  float oacc[8][4] = {};
  float m0r = -1e30f, m1r = -1e30f, l0r = 0.f, l1r = 0.f;

  for (int kt = 0; kt < ntiles; kt++) {
    const int kbase = kt * 64;
    const uint32_t kb16 = sb + ASTG0 + (kt & 1) * ASTG_SZ;
    const uint32_t vb16 = kb16 + AKV_COMP;

    CP_WAIT0();
    __syncthreads();
    if (kt + 1 < ntiles) {
      issue_tile((kt + 1) & 1, kbase + 64);
      CP_COMMIT();
    }

    float sc[8][4];
#pragma unroll
    for (int nt = 0; nt < 8; nt++)
#pragma unroll
      for (int c = 0; c < 4; c++) sc[nt][c] = 0.f;
#pragma unroll
    for (int ks = 0; ks < 4; ks++) {
      uint32_t kf[16];
#pragma unroll
      for (int np = 0; np < 4; np++) {
        uint32_t rb = (np * 16 + b_row) * (RS * 2) + ks * 32 + b_koff;
        LDMX4(kf[np * 4 + 0], kf[np * 4 + 1], kf[np * 4 + 2], kf[np * 4 + 3],
              kb16 + rb);
      }
#pragma unroll
      for (int nt = 0; nt < 8; nt++) {
        float* c = sc[nt];
        mma_f16(c[0], c[1], c[2], c[3], qf[ks][0], qf[ks][1], qf[ks][2],
                qf[ks][3], kf[nt * 2], kf[nt * 2 + 1]);
      }
    }

#pragma unroll
    for (int nt = 0; nt < 8; nt++)
#pragma unroll
      for (int c = 0; c < 4; c++) sc[nt][c] *= SC2;
    if (kbase + 64 > vlen) {
#pragma unroll
      for (int nt = 0; nt < 8; nt++) {
        int k0 = kbase + nt * 8 + cb;
        if (k0 >= vlen) { sc[nt][0] = -1e30f; sc[nt][2] = -1e30f; }
        if (k0 + 1 >= vlen) { sc[nt][1] = -1e30f; sc[nt][3] = -1e30f; }
      }
    }

    float rm0 = -1e30f, rm1 = -1e30f;
#pragma unroll
    for (int nt = 0; nt < 8; nt++) {
      rm0 = fmaxf(rm0, fmaxf(sc[nt][0], sc[nt][1]));
      rm1 = fmaxf(rm1, fmaxf(sc[nt][2], sc[nt][3]));
    }
    rm0 = fmaxf(rm0, __shfl_xor_sync(0xffffffffu, rm0, 1));
    rm0 = fmaxf(rm0, __shfl_xor_sync(0xffffffffu, rm0, 2));
    rm1 = fmaxf(rm1, __shfl_xor_sync(0xffffffffu, rm1, 1));
    rm1 = fmaxf(rm1, __shfl_xor_sync(0xffffffffu, rm1, 2));
    float mn0 = fmaxf(m0r, rm0), mn1 = fmaxf(m1r, rm1);
    float corr0 = exp2f(m0r - mn0), corr1 = exp2f(m1r - mn1);

    uint32_t pf[8][2];
    float rs0 = 0.f, rs1 = 0.f;
#pragma unroll
    for (int nt = 0; nt < 8; nt++) {
      float p0 = exp2f(sc[nt][0] - mn0);
      float p1 = exp2f(sc[nt][1] - mn0);
      float p2 = exp2f(sc[nt][2] - mn1);
      float p3 = exp2f(sc[nt][3] - mn1);
      rs0 += p0 + p1;
      rs1 += p2 + p3;
      pf[nt][0] = pack_f16(p0, p1);
      pf[nt][1] = pack_f16(p2, p3);
    }
    rs0 += __shfl_xor_sync(0xffffffffu, rs0, 1);
    rs0 += __shfl_xor_sync(0xffffffffu, rs0, 2);
    rs1 += __shfl_xor_sync(0xffffffffu, rs1, 1);
    rs1 += __shfl_xor_sync(0xffffffffu, rs1, 2);
    l0r = l0r * corr0 + rs0;
    l1r = l1r * corr1 + rs1;
    m0r = mn0;
    m1r = mn1;
#pragma unroll
    for (int nt = 0; nt < 8; nt++) {
      oacc[nt][0] *= corr0;
      oacc[nt][1] *= corr0;
      oacc[nt][2] *= corr1;
      oacc[nt][3] *= corr1;
    }

#pragma unroll
    for (int ks = 0; ks < 4; ks++) {
      uint32_t vf[16];
#pragma unroll
      for (int np = 0; np < 4; np++) {
        uint32_t rv = (ks * 16 + v_row) * (RS * 2) + np * 32 + v_col;
        LDMX4T(vf[np * 4 + 0], vf[np * 4 + 1], vf[np * 4 + 2], vf[np * 4 + 3],
               vb16 + rv);
      }
      uint32_t a0 = pf[2 * ks][0], a1 = pf[2 * ks][1];
      uint32_t a2 = pf[2 * ks + 1][0], a3 = pf[2 * ks + 1][1];
#pragma unroll
      for (int nt = 0; nt < 8; nt++) {
        float* c = oacc[nt];
        mma_f16(c[0], c[1], c[2], c[3], a0, a1, a2, a3, vf[nt * 2],
                vf[nt * 2 + 1]);
      }
    }
  }

  float inv0 = 1.f / l0r, inv1 = 1.f / l1r;
  int r0 = q0 + wid * 16 + (l >> 2);
#pragma unroll
  for (int nt = 0; nt < 8; nt++) {
    int col = h * DH + nt * 8 + cb;
    size_t i0 = (size_t)(b * S + r0) * HID + col;
    size_t i1 = (size_t)(b * S + r0 + 8) * HID + col;
    *(uint32_t*)&O16[i0] = pack_f16(oacc[nt][0] * inv0, oacc[nt][1] * inv0);
    *(uint32_t*)&O16[i1] = pack_f16(oacc[nt][2] * inv1, oacc[nt][3] * inv1);
  }
}

// ---------------------------------------------------------------------------
extern "C" void kernel_launch(void* const* d_in, const int* in_sizes, int n_in,
                              void* d_out, int out_size) {
  const float* queries = (const float*)d_in[0];
  const float* keys    = (const float*)d_in[1];
  const float* values  = (const float*)d_in[2];
  const int*   vlens   = (const int*)d_in[3];
  const float* W[4]    = {(const float*)d_in[4], (const float*)d_in[5],
                          (const float*)d_in[6], (const float*)d_in[7]};
  float* out = (float*)d_out;

  __half *whb, *wlb, *q16, *k16, *v16, *o16;
  cudaGetSymbolAddress((void**)&whb, g_wh16);
  cudaGetSymbolAddress((void**)&wlb, g_wl16);
  cudaGetSymbolAddress((void**)&q16, g_q16);
  cudaGetSymbolAddress((void**)&k16, g_k16);
  cudaGetSymbolAddress((void**)&v16, g_v16);
  cudaGetSymbolAddress((void**)&o16, g_o16);
  const int WSZ = HID * HID;

  cudaFuncSetAttribute(gemm_tc_hmma<true, true>,
                       cudaFuncAttributeMaxDynamicSharedMemorySize, GEMM_SMEM);
  cudaFuncSetAttribute(gemm_tc_hmma<false, false>,
                       cudaFuncAttributeMaxDynamicSharedMemorySize, GEMM_SMEM);
  cudaFuncSetAttribute(attn_hmma,
                       cudaFuncAttributeMaxDynamicSharedMemorySize, ATTN_SMEM);

  // --- one batched weight split (Wq, Wk, Wv, Wo) -> fp16 hi/lo ---
  SplitBatch wsb = {};
  for (int i = 0; i < 4; i++) {
    wsb.src[i] = W[i];
    wsb.hi[i] = whb + i * WSZ;
    wsb.lo[i] = wlb + i * WSZ;
  }
  split_batch_kernel<<<dim3(WSZ / 4 / 256, 4), 256>>>(wsb, WSZ / 4);

  // --- Q/K/V projections (fp16x2), fp16 outputs; K/V vlen tiles skipped ---
  GemmBatch gp = {};
  gp.af[0] = queries; gp.af[1] = keys; gp.af[2] = values;
  for (int i = 0; i < 3; i++) {
    gp.wh[i] = whb + i * WSZ;
    gp.wl[i] = wlb + i * WSZ;
  }
  gp.c16[0] = q16; gp.c16[1] = k16; gp.c16[2] = v16;
  gp.vlens = vlens;
  gemm_tc_hmma<true, true>
      <<<dim3(HID / 128, M / 128, 3), 256, GEMM_SMEM>>>(gp);

  // --- attention (fp16 single-term, LPT batch order) ---
  attn_hmma<<<dim3(S / 128, NH, B), 256, ATTN_SMEM>>>(q16, k16, v16, vlens,
                                                      o16);

  // --- output projection (fp16x2 on fp16 O, fp32 out) ---
  GemmBatch go = {};
  go.a16 = o16;
  go.wh[0] = whb + 3 * WSZ;
  go.wl[0] = wlb + 3 * WSZ;
  go.c = out;
  go.vlens = nullptr;
  gemm_tc_hmma<false, false>
      <<<dim3(HID / 128, M / 128, 1), 256, GEMM_SMEM>>>(go);
}